// round 1
// baseline (speedup 1.0000x reference)
#include <cuda_runtime.h>
#include <math.h>
#include <stdint.h>

#define BB 16
#define TT 800
#define EE 512
#define DD 1024
#define AA 512
#define OO 5000
#define LL 97          // olength = LMAX + 1
#define KS 8           // k-split for skinny gemms
#define SOSEOS 4999

// ---------------- scratch (static __device__, no allocs) ----------------
__device__ float g_preenc[BB * TT * AA];            // 6.55M
__device__ float g_W0T[2560 * 4096];                // packed k-major float4-interleaved
__device__ float g_W1T[2048 * 4096];
__device__ float g_WdT[1024 * 512];
__device__ float g_b0[4096];
__device__ float g_b1[4096];
__device__ float g_eys[BB * LL * DD];
__device__ float g_z0[BB * DD], g_c0[BB * DD], g_z1[BB * DD], g_c1[BB * DD];
__device__ float g_x0[BB * 2560];                   // [ey | att_c | z0]
__device__ float g_x1[BB * 2048];                   // [z0_new | z1_old]
__device__ float g_escore[BB * TT];
__device__ float g_attw[BB * TT];
__device__ float g_partd[KS * BB * AA];
__device__ float g_part0[KS * BB * 4096];
__device__ float g_part1[KS * BB * 4096];
__device__ float g_zall[BB * LL * DD];
__device__ float g_logits[(size_t)BB * LL * OO];    // 7.76M
__device__ float g_nll[BB * LL];

// ---------------- helpers ----------------
__device__ __forceinline__ float tanh_ap(float x) {
    float y;
    asm("tanh.approx.f32 %0, %1;" : "=f"(y) : "f"(x));
    return y;
}
__device__ __forceinline__ float sigm(float x) { return 1.0f / (1.0f + __expf(-x)); }

// ---------------- prep: pack weights k-major, float4-interleaved ----------------
// layout: W*T[(k>>2)*(N*4) + j*4 + (k&3)]   -> float4 load at ((k>>2)*N + j)
__global__ void pack_w0(const float* __restrict__ Wih0, const float* __restrict__ Whh0) {
    int idx = blockIdx.x * 256 + threadIdx.x;
    if (idx >= 4096 * 2560) return;
    int j = idx / 2560, k = idx % 2560;
    float v = (k < 1536) ? Wih0[j * 1536 + k] : Whh0[j * 1024 + (k - 1536)];
    g_W0T[(size_t)(k >> 2) * 16384 + j * 4 + (k & 3)] = v;
}
__global__ void pack_w1(const float* __restrict__ Wih1, const float* __restrict__ Whh1) {
    int idx = blockIdx.x * 256 + threadIdx.x;
    if (idx >= 4096 * 2048) return;
    int j = idx / 2048, k = idx % 2048;
    float v = (k < 1024) ? Wih1[j * 1024 + k] : Whh1[j * 1024 + (k - 1024)];
    g_W1T[(size_t)(k >> 2) * 16384 + j * 4 + (k & 3)] = v;
}
__global__ void pack_wd(const float* __restrict__ Wdec) {
    int idx = blockIdx.x * 256 + threadIdx.x;
    if (idx >= 512 * 1024) return;
    int j = idx / 1024, k = idx % 1024;
    g_WdT[(k >> 2) * 2048 + j * 4 + (k & 3)] = Wdec[j * 1024 + k];
}
__global__ void prep_misc(const float* __restrict__ bih0, const float* __restrict__ bhh0,
                          const float* __restrict__ bih1, const float* __restrict__ bhh1,
                          const int* __restrict__ ys_pad, const float* __restrict__ embed) {
    int idx = blockIdx.x * 256 + threadIdx.x;
    if (idx < 4096) {
        g_b0[idx] = bih0[idx] + bhh0[idx];
        g_b1[idx] = bih1[idx] + bhh1[idx];
    }
    if (idx < BB * DD) {
        g_z0[idx] = 0.f; g_c0[idx] = 0.f; g_z1[idx] = 0.f; g_c1[idx] = 0.f;
    }
    if (idx < BB * LL * DD) {
        int m = idx >> 10;     // row (b,l)
        int d = idx & 1023;
        int b = m / LL, l = m % LL;
        int tok = (l == 0) ? SOSEOS : ys_pad[b * 96 + l - 1];
        g_eys[idx] = embed[(size_t)tok * DD + d];
    }
}

// ---------------- generic NT GEMM: C[M,N] = A[M,K] * B[N,K]^T + bias[n] ----------------
// 128x128 tile, BK=8, 256 threads, 8x8 per thread
__global__ __launch_bounds__(256) void gemm_nt(const float* __restrict__ A,
                                               const float* __restrict__ Bm,
                                               const float* __restrict__ bias,
                                               float* __restrict__ C,
                                               int M, int N, int K) {
    __shared__ float As[8][128];
    __shared__ float Bs[8][128];
    int tid = threadIdx.x;
    int m0 = blockIdx.y * 128, n0 = blockIdx.x * 128;
    int lr = tid >> 1;            // 0..127
    int lk = (tid & 1) * 4;       // 0 or 4
    int tx = tid & 15, ty = tid >> 4;
    float acc[8][8];
#pragma unroll
    for (int i = 0; i < 8; i++)
#pragma unroll
        for (int j = 0; j < 8; j++) acc[i][j] = 0.f;

    for (int k0 = 0; k0 < K; k0 += 8) {
        float4 av = make_float4(0.f, 0.f, 0.f, 0.f);
        float4 bv = make_float4(0.f, 0.f, 0.f, 0.f);
        if (m0 + lr < M) av = *(const float4*)&A[(size_t)(m0 + lr) * K + k0 + lk];
        if (n0 + lr < N) bv = *(const float4*)&Bm[(size_t)(n0 + lr) * K + k0 + lk];
        __syncthreads();
        As[lk + 0][lr] = av.x; As[lk + 1][lr] = av.y; As[lk + 2][lr] = av.z; As[lk + 3][lr] = av.w;
        Bs[lk + 0][lr] = bv.x; Bs[lk + 1][lr] = bv.y; Bs[lk + 2][lr] = bv.z; Bs[lk + 3][lr] = bv.w;
        __syncthreads();
#pragma unroll
        for (int kk = 0; kk < 8; kk++) {
            float a[8], b[8];
            *(float4*)(a)     = *(const float4*)&As[kk][ty * 8];
            *(float4*)(a + 4) = *(const float4*)&As[kk][ty * 8 + 4];
            *(float4*)(b)     = *(const float4*)&Bs[kk][tx * 8];
            *(float4*)(b + 4) = *(const float4*)&Bs[kk][tx * 8 + 4];
#pragma unroll
            for (int i = 0; i < 8; i++)
#pragma unroll
                for (int j = 0; j < 8; j++) acc[i][j] += a[i] * b[j];
        }
    }
#pragma unroll
    for (int i = 0; i < 8; i++) {
        int m = m0 + ty * 8 + i;
        if (m >= M) continue;
#pragma unroll
        for (int j = 0; j < 8; j++) {
            int n = n0 + tx * 8 + j;
            if (n < N) C[(size_t)m * N + n] = acc[i][j] + bias[n];
        }
    }
}

// ---------------- skinny GEMM: part[s][b][j] = sum_{k in chunk s} x[b][k] * W[j][k] ----------------
// WT packed k-major float4-interleaved. grid (N/128, KS), 128 threads.
__global__ __launch_bounds__(128) void skinny16(const float* __restrict__ x,
                                                const float* __restrict__ WT,
                                                float* __restrict__ part,
                                                int K, int N, int kchunk) {
    __shared__ float xs[16 * 320];
    int j = blockIdx.x * 128 + threadIdx.x;
    int kc = blockIdx.y * kchunk;
    for (int i = threadIdx.x; i < 16 * kchunk; i += 128) {
        int b = i / kchunk, kk = i - b * kchunk;
        xs[i] = x[b * K + kc + kk];
    }
    __syncthreads();
    float acc[16];
#pragma unroll
    for (int b = 0; b < 16; b++) acc[b] = 0.f;

    const float4* wp = (const float4*)WT;
#pragma unroll 2
    for (int kk = 0; kk < kchunk; kk += 4) {
        float4 w = wp[(size_t)((kc + kk) >> 2) * N + j];
#pragma unroll
        for (int b = 0; b < 16; b++) {
            float4 xv = *(const float4*)&xs[b * kchunk + kk];
            float s = acc[b];
            s = fmaf(w.x, xv.x, s);
            s = fmaf(w.y, xv.y, s);
            s = fmaf(w.z, xv.z, s);
            s = fmaf(w.w, xv.w, s);
            acc[b] = s;
        }
    }
    float* po = part + (size_t)blockIdx.y * (16 * N);
#pragma unroll
    for (int b = 0; b < 16; b++) po[b * N + j] = acc[b];
}

// ---------------- attention score: e[b,t] = sum_a g[a]*tanh(pre_enc + dec_proj) ----------------
// grid (16 t-chunks of 50, 16 b), 256 threads (8 warps)
__global__ __launch_bounds__(256) void attn_score(const float* __restrict__ gvec) {
    __shared__ float dp[512];
    __shared__ float gv[512];
    int b = blockIdx.y;
    int t0 = blockIdx.x * 50;
    int tid = threadIdx.x;
    for (int a = tid; a < 512; a += 256) {
        float s = 0.f;
#pragma unroll
        for (int sp = 0; sp < KS; sp++) s += g_partd[sp * (BB * AA) + b * AA + a];
        dp[a] = s;
        gv[a] = gvec[a];
    }
    __syncthreads();
    int warp = tid >> 5, lane = tid & 31;
    for (int t = t0 + warp; t < t0 + 50; t += 8) {
        const float4* pe = (const float4*)&g_preenc[((size_t)b * TT + t) * AA];
        float acc = 0.f;
#pragma unroll
        for (int g = 0; g < 4; g++) {
            int q = lane + 32 * g;
            float4 v = pe[q];
            float4 d = *(const float4*)&dp[4 * q];
            float4 gg = *(const float4*)&gv[4 * q];
            acc += gg.x * tanh_ap(v.x + d.x);
            acc += gg.y * tanh_ap(v.y + d.y);
            acc += gg.z * tanh_ap(v.z + d.z);
            acc += gg.w * tanh_ap(v.w + d.w);
        }
#pragma unroll
        for (int off = 16; off; off >>= 1) acc += __shfl_xor_sync(0xffffffffu, acc, off);
        if (lane == 0) g_escore[b * TT + t] = acc;
    }
}

// ---------------- softmax + build x0 (ey | zero att_c slot | z0) ----------------
__global__ __launch_bounds__(256) void softmax_build(const int* __restrict__ hlens, int l) {
    __shared__ float red[256];
    int b = blockIdx.x, tid = threadIdx.x;
    int hlen = hlens[b];
    const float* e = &g_escore[b * TT];
    float mx = -1e30f;
    for (int t = tid; t < TT; t += 256)
        if (t < hlen) mx = fmaxf(mx, e[t]);
    red[tid] = mx; __syncthreads();
    for (int s = 128; s; s >>= 1) { if (tid < s) red[tid] = fmaxf(red[tid], red[tid + s]); __syncthreads(); }
    mx = red[0]; __syncthreads();
    float sum = 0.f;
    for (int t = tid; t < TT; t += 256)
        if (t < hlen) sum += __expf(2.0f * (e[t] - mx));
    red[tid] = sum; __syncthreads();
    for (int s = 128; s; s >>= 1) { if (tid < s) red[tid] += red[tid + s]; __syncthreads(); }
    float inv = 1.0f / red[0];
    for (int t = tid; t < TT; t += 256)
        g_attw[b * TT + t] = (t < hlen) ? __expf(2.0f * (e[t] - mx)) * inv : 0.f;
    // build x0: [0,1024)=ey_l ; [1024,1536)=0 (att_c accumulated by atomics) ; [1536,2560)=z0
    const float* ey = &g_eys[((size_t)b * LL + l) * DD];
    for (int i = tid; i < DD; i += 256) {
        g_x0[b * 2560 + i] = ey[i];
        g_x0[b * 2560 + 1536 + i] = g_z0[b * DD + i];
    }
    for (int i = tid; i < 512; i += 256) g_x0[b * 2560 + 1024 + i] = 0.f;
}

// ---------------- att_c accumulation: x0[b][1024+e] += sum_t w[b,t]*hs[b,t,e] ----------------
// grid 256 = b(16) x echunk(4) x tsplit(4), 128 threads
__global__ __launch_bounds__(128) void attc_kernel(const float* __restrict__ hs) {
    __shared__ float w[200];
    int bx = blockIdx.x;
    int b = bx >> 4, ec = (bx >> 2) & 3, ts = bx & 3;
    int tid = threadIdx.x;
    int t0 = ts * 200;
    for (int i = tid; i < 200; i += 128) w[i] = g_attw[b * TT + t0 + i];
    __syncthreads();
    int e = ec * 128 + tid;
    const float* hp = &hs[((size_t)b * TT + t0) * EE + e];
    float acc = 0.f;
#pragma unroll 4
    for (int tt = 0; tt < 200; tt++) acc += w[tt] * hp[(size_t)tt * EE];
    atomicAdd(&g_x0[b * 2560 + 1024 + e], acc);
}

// ---------------- LSTM cells ----------------
__global__ __launch_bounds__(256) void cell0(void) {
    int u = blockIdx.x * 256 + threadIdx.x;   // 16*1024
    int b = u >> 10, d = u & 1023;
    float gi = g_b0[d], gf = g_b0[1024 + d], gg = g_b0[2048 + d], go = g_b0[3072 + d];
#pragma unroll
    for (int s = 0; s < KS; s++) {
        const float* p = &g_part0[(size_t)s * (BB * 4096) + b * 4096];
        gi += p[d]; gf += p[1024 + d]; gg += p[2048 + d]; go += p[3072 + d];
    }
    float c = sigm(gf) * g_c0[u] + sigm(gi) * tanh_ap(gg);
    float h = sigm(go) * tanh_ap(c);
    g_c0[u] = c;
    g_z0[u] = h;
    g_x1[b * 2048 + d] = h;
    g_x1[b * 2048 + 1024 + d] = g_z1[u];
}
__global__ __launch_bounds__(256) void cell1(int l) {
    int u = blockIdx.x * 256 + threadIdx.x;
    int b = u >> 10, d = u & 1023;
    float gi = g_b1[d], gf = g_b1[1024 + d], gg = g_b1[2048 + d], go = g_b1[3072 + d];
#pragma unroll
    for (int s = 0; s < KS; s++) {
        const float* p = &g_part1[(size_t)s * (BB * 4096) + b * 4096];
        gi += p[d]; gf += p[1024 + d]; gg += p[2048 + d]; go += p[3072 + d];
    }
    float c = sigm(gf) * g_c1[u] + sigm(gi) * tanh_ap(gg);
    float h = sigm(go) * tanh_ap(c);
    g_c1[u] = c;
    g_z1[u] = h;
    g_zall[((size_t)b * LL + l) * DD + d] = h;
}

// ---------------- NLL per (b,l) row + final reduce ----------------
__global__ __launch_bounds__(256) void nll_kernel(const int* __restrict__ ys_pad) {
    __shared__ float red[256];
    int m = blockIdx.x, tid = threadIdx.x;
    int b = m / LL, l = m % LL;
    const float* row = &g_logits[(size_t)m * OO];
    float mx = -1e30f;
    for (int i = tid; i < OO; i += 256) mx = fmaxf(mx, row[i]);
    red[tid] = mx; __syncthreads();
    for (int s = 128; s; s >>= 1) { if (tid < s) red[tid] = fmaxf(red[tid], red[tid + s]); __syncthreads(); }
    mx = red[0]; __syncthreads();
    float sum = 0.f;
    for (int i = tid; i < OO; i += 256) sum += __expf(row[i] - mx);
    red[tid] = sum; __syncthreads();
    for (int s = 128; s; s >>= 1) { if (tid < s) red[tid] += red[tid + s]; __syncthreads(); }
    if (tid == 0) {
        int tgt = (l < 96) ? ys_pad[b * 96 + l] : SOSEOS;
        g_nll[m] = logf(red[0]) + mx - row[tgt];
    }
}
__global__ __launch_bounds__(256) void finalize(float* out) {
    __shared__ float red[256];
    int tid = threadIdx.x;
    float acc = 0.f;
    for (int i = tid; i < BB * LL; i += 256) acc += g_nll[i];
    red[tid] = acc; __syncthreads();
    for (int s = 128; s; s >>= 1) { if (tid < s) red[tid] += red[tid + s]; __syncthreads(); }
    if (tid == 0) out[0] = red[0] * (96.0f / (float)(BB * LL));
}

// ---------------- launch ----------------
extern "C" void kernel_launch(void* const* d_in, const int* in_sizes, int n_in,
                              void* d_out, int out_size) {
    const float* hs_pad = (const float*)d_in[0];
    const int*   hlens  = (const int*)d_in[1];
    const int*   ys_pad = (const int*)d_in[2];
    const float* embed  = (const float*)d_in[3];
    const float* W_ih0  = (const float*)d_in[4];
    const float* W_hh0  = (const float*)d_in[5];
    const float* b_ih0  = (const float*)d_in[6];
    const float* b_hh0  = (const float*)d_in[7];
    const float* W_ih1  = (const float*)d_in[8];
    const float* W_hh1  = (const float*)d_in[9];
    const float* b_ih1  = (const float*)d_in[10];
    const float* b_hh1  = (const float*)d_in[11];
    const float* W_enc  = (const float*)d_in[12];
    const float* b_enc  = (const float*)d_in[13];
    const float* W_dec  = (const float*)d_in[14];
    const float* gvec   = (const float*)d_in[15];
    const float* W_out  = (const float*)d_in[16];
    const float* b_out  = (const float*)d_in[17];
    float* out = (float*)d_out;

    pack_w0<<<(4096 * 2560 + 255) / 256, 256>>>(W_ih0, W_hh0);
    pack_w1<<<(4096 * 2048 + 255) / 256, 256>>>(W_ih1, W_hh1);
    pack_wd<<<(512 * 1024 + 255) / 256, 256>>>(W_dec);
    prep_misc<<<(BB * LL * DD + 255) / 256, 256>>>(b_ih0, b_hh0, b_ih1, b_hh1, ys_pad, embed);

    // pre_enc = hs_pad @ W_enc^T + b_enc   (M=12800, N=512, K=512)
    gemm_nt<<<dim3(4, 100), 256>>>(hs_pad, W_enc, b_enc, g_preenc, BB * TT, AA, EE);

    for (int l = 0; l < LL; l++) {
        // dec_proj = z0 @ W_dec^T  (N=512, K=1024)
        skinny16<<<dim3(4, KS), 128>>>(g_z0, g_WdT, g_partd, 1024, 512, 128);
        attn_score<<<dim3(16, 16), 256>>>(gvec);
        softmax_build<<<16, 256>>>(hlens, l);
        attc_kernel<<<256, 128>>>(hs_pad);
        // gates0 = x0 @ [W_ih0|W_hh0]^T  (N=4096, K=2560)
        skinny16<<<dim3(32, KS), 128>>>(g_x0, g_W0T, g_part0, 2560, 4096, 320);
        cell0<<<64, 256>>>();
        // gates1 = x1 @ [W_ih1|W_hh1]^T  (N=4096, K=2048)
        skinny16<<<dim3(32, KS), 128>>>(g_x1, g_W1T, g_part1, 2048, 4096, 256);
        cell1<<<64, 256>>>(l);
    }

    // logits = z_all @ W_out^T + b_out  (M=1552, N=5000, K=1024)
    gemm_nt<<<dim3(40, 13), 256>>>(g_zall, W_out, b_out, g_logits, BB * LL, OO, DD);
    nll_kernel<<<BB * LL, 256>>>(ys_pad);
    finalize<<<1, 256>>>(out);
}

// round 2
// speedup vs baseline: 1.4467x; 1.4467x over previous
#include <cuda_runtime.h>
#include <cuda_bf16.h>
#include <math.h>
#include <stdint.h>

#define BB 16
#define TT 800
#define EE 512
#define DD 1024
#define AA 512
#define OO 5000
#define LL 97          // olength = LMAX + 1
#define KS 8           // k-split for skinny gemms
#define SOSEOS 4999

// ---------------- scratch (static __device__, no allocs) ----------------
__device__ __align__(16) unsigned short g_preenc_bf[BB * TT * AA];   // 13MB
__device__ __align__(16) unsigned short g_hs_bf[BB * TT * EE];       // 13MB
__device__ __align__(16) unsigned short g_W0T[2560 * 4096];          // 20MB bf16 packed k8-interleaved
__device__ __align__(16) unsigned short g_W1T[2048 * 4096];          // 16MB
__device__ __align__(16) unsigned short g_WdT[1024 * 512];           // 1MB
__device__ float g_b0[4096];
__device__ float g_b1[4096];
__device__ float g_eys[BB * LL * DD];
__device__ float g_z0[BB * DD], g_c0[BB * DD], g_z1[BB * DD], g_c1[BB * DD];
__device__ float g_x0[BB * 2560];                   // [ey | att_c | z0]
__device__ float g_x1[BB * 2048];                   // [z0_new | z1_old]
__device__ float g_escore[BB * TT];
__device__ float g_attw[BB * TT];
__device__ float g_partd[KS * BB * AA];
__device__ float g_part0[KS * BB * 4096];
__device__ float g_part1[KS * BB * 4096];
__device__ float g_zall[BB * LL * DD];
__device__ float g_logits[(size_t)BB * LL * OO];    // 31MB
__device__ float g_nll[BB * LL];

// ---------------- helpers ----------------
__device__ __forceinline__ float tanh_ap(float x) {
    float y;
    asm("tanh.approx.f32 %0, %1;" : "=f"(y) : "f"(x));
    return y;
}
__device__ __forceinline__ float sigm(float x) { return 1.0f / (1.0f + __expf(-x)); }
__device__ __forceinline__ unsigned short f2bf(float v) {
    return __bfloat16_as_ushort(__float2bfloat16_rn(v));
}
// unpack 8 bf16 (one uint4) to 8 floats: bf16 == high half of fp32
__device__ __forceinline__ void unp8(uint4 w, float* f) {
    f[0] = __uint_as_float(w.x << 16); f[1] = __uint_as_float(w.x & 0xffff0000u);
    f[2] = __uint_as_float(w.y << 16); f[3] = __uint_as_float(w.y & 0xffff0000u);
    f[4] = __uint_as_float(w.z << 16); f[5] = __uint_as_float(w.z & 0xffff0000u);
    f[6] = __uint_as_float(w.w << 16); f[7] = __uint_as_float(w.w & 0xffff0000u);
}

// ---------------- prep: pack weights bf16, k-major 8-interleaved ----------------
// layout: W*T[(k>>3)*(N*8) + j*8 + (k&7)]  -> uint4 load at ((k>>3)*N + j)
__global__ void pack_w0(const float* __restrict__ Wih0, const float* __restrict__ Whh0) {
    int idx = blockIdx.x * 256 + threadIdx.x;
    if (idx >= 4096 * 2560) return;
    int j = idx / 2560, k = idx % 2560;
    float v = (k < 1536) ? Wih0[j * 1536 + k] : Whh0[j * 1024 + (k - 1536)];
    g_W0T[(size_t)(k >> 3) * 32768 + j * 8 + (k & 7)] = f2bf(v);
}
__global__ void pack_w1(const float* __restrict__ Wih1, const float* __restrict__ Whh1) {
    int idx = blockIdx.x * 256 + threadIdx.x;
    if (idx >= 4096 * 2048) return;
    int j = idx / 2048, k = idx % 2048;
    float v = (k < 1024) ? Wih1[j * 1024 + k] : Whh1[j * 1024 + (k - 1024)];
    g_W1T[(size_t)(k >> 3) * 32768 + j * 8 + (k & 7)] = f2bf(v);
}
__global__ void pack_wd(const float* __restrict__ Wdec) {
    int idx = blockIdx.x * 256 + threadIdx.x;
    if (idx >= 512 * 1024) return;
    int j = idx / 1024, k = idx % 1024;
    g_WdT[(k >> 3) * 4096 + j * 8 + (k & 7)] = f2bf(Wdec[j * 1024 + k]);
}
__global__ void convert_hs(const float* __restrict__ hs) {
    int idx = blockIdx.x * 256 + threadIdx.x;
    if (idx < BB * TT * EE) g_hs_bf[idx] = f2bf(hs[idx]);
}
__global__ void prep_misc(const float* __restrict__ bih0, const float* __restrict__ bhh0,
                          const float* __restrict__ bih1, const float* __restrict__ bhh1,
                          const int* __restrict__ ys_pad, const float* __restrict__ embed) {
    int idx = blockIdx.x * 256 + threadIdx.x;
    if (idx < 4096) {
        g_b0[idx] = bih0[idx] + bhh0[idx];
        g_b1[idx] = bih1[idx] + bhh1[idx];
    }
    if (idx < BB * DD) {
        g_z0[idx] = 0.f; g_c0[idx] = 0.f; g_z1[idx] = 0.f; g_c1[idx] = 0.f;
    }
    if (idx < BB * LL * DD) {
        int m = idx >> 10;     // row (b,l)
        int d = idx & 1023;
        int b = m / LL, l = m % LL;
        int tok = (l == 0) ? SOSEOS : ys_pad[b * 96 + l - 1];
        g_eys[idx] = embed[(size_t)tok * DD + d];
    }
}

// ---------------- generic NT GEMM: C[M,N] = A[M,K] * B[N,K]^T + bias[n] ----------------
// 128x128 tile, BK=8, 256 threads, 8x8 per thread. STORE_BF=0 -> fp32 C, 1 -> bf16 C.
template <int STORE_BF>
__global__ __launch_bounds__(256) void gemm_nt(const float* __restrict__ A,
                                               const float* __restrict__ Bm,
                                               const float* __restrict__ bias,
                                               float* __restrict__ C,
                                               unsigned short* __restrict__ Cbf,
                                               int M, int N, int K) {
    __shared__ float As[8][128];
    __shared__ float Bs[8][128];
    int tid = threadIdx.x;
    int m0 = blockIdx.y * 128, n0 = blockIdx.x * 128;
    int lr = tid >> 1;            // 0..127
    int lk = (tid & 1) * 4;       // 0 or 4
    int tx = tid & 15, ty = tid >> 4;
    float acc[8][8];
#pragma unroll
    for (int i = 0; i < 8; i++)
#pragma unroll
        for (int j = 0; j < 8; j++) acc[i][j] = 0.f;

    for (int k0 = 0; k0 < K; k0 += 8) {
        float4 av = make_float4(0.f, 0.f, 0.f, 0.f);
        float4 bv = make_float4(0.f, 0.f, 0.f, 0.f);
        if (m0 + lr < M) av = *(const float4*)&A[(size_t)(m0 + lr) * K + k0 + lk];
        if (n0 + lr < N) bv = *(const float4*)&Bm[(size_t)(n0 + lr) * K + k0 + lk];
        __syncthreads();
        As[lk + 0][lr] = av.x; As[lk + 1][lr] = av.y; As[lk + 2][lr] = av.z; As[lk + 3][lr] = av.w;
        Bs[lk + 0][lr] = bv.x; Bs[lk + 1][lr] = bv.y; Bs[lk + 2][lr] = bv.z; Bs[lk + 3][lr] = bv.w;
        __syncthreads();
#pragma unroll
        for (int kk = 0; kk < 8; kk++) {
            float a[8], b[8];
            *(float4*)(a)     = *(const float4*)&As[kk][ty * 8];
            *(float4*)(a + 4) = *(const float4*)&As[kk][ty * 8 + 4];
            *(float4*)(b)     = *(const float4*)&Bs[kk][tx * 8];
            *(float4*)(b + 4) = *(const float4*)&Bs[kk][tx * 8 + 4];
#pragma unroll
            for (int i = 0; i < 8; i++)
#pragma unroll
                for (int j = 0; j < 8; j++) acc[i][j] += a[i] * b[j];
        }
    }
#pragma unroll
    for (int i = 0; i < 8; i++) {
        int m = m0 + ty * 8 + i;
        if (m >= M) continue;
#pragma unroll
        for (int j = 0; j < 8; j++) {
            int n = n0 + tx * 8 + j;
            if (n < N) {
                float v = acc[i][j] + bias[n];
                if (STORE_BF) Cbf[(size_t)m * N + n] = f2bf(v);
                else          C[(size_t)m * N + n] = v;
            }
        }
    }
}

// ---------------- skinny GEMM (bf16 weights): part[s][b][j] = sum_k x[b][k]*W[j][k] ----------------
// WT packed k-major 8-interleaved bf16. grid (N/128, KS), 128 threads.
__global__ __launch_bounds__(128) void skinny_bf(const float* __restrict__ x,
                                                 const unsigned short* __restrict__ WT,
                                                 float* __restrict__ part,
                                                 int K, int N, int kchunk) {
    __shared__ float xs[16 * 320];
    int j = blockIdx.x * 128 + threadIdx.x;
    int kc = blockIdx.y * kchunk;
    for (int i = threadIdx.x; i < 16 * kchunk; i += 128) {
        int b = i / kchunk, kk = i - b * kchunk;
        xs[i] = x[b * K + kc + kk];
    }
    __syncthreads();
    float acc[16];
#pragma unroll
    for (int b = 0; b < 16; b++) acc[b] = 0.f;

    const uint4* wp = (const uint4*)WT;
#pragma unroll 4
    for (int kk = 0; kk < kchunk; kk += 8) {
        uint4 w = wp[(size_t)((kc + kk) >> 3) * N + j];
        float wf[8];
        unp8(w, wf);
#pragma unroll
        for (int b = 0; b < 16; b++) {
            float4 xa = *(const float4*)&xs[b * kchunk + kk];
            float4 xb = *(const float4*)&xs[b * kchunk + kk + 4];
            float s = acc[b];
            s = fmaf(wf[0], xa.x, s); s = fmaf(wf[1], xa.y, s);
            s = fmaf(wf[2], xa.z, s); s = fmaf(wf[3], xa.w, s);
            s = fmaf(wf[4], xb.x, s); s = fmaf(wf[5], xb.y, s);
            s = fmaf(wf[6], xb.z, s); s = fmaf(wf[7], xb.w, s);
            acc[b] = s;
        }
    }
    float* po = part + (size_t)blockIdx.y * (16 * N);
#pragma unroll
    for (int b = 0; b < 16; b++) po[b * N + j] = acc[b];
}

// ---------------- attention score: e[b,t] = sum_a g[a]*tanh(pre_enc + dec_proj) ----------------
// grid (16 t-chunks of 50, 16 b), 256 threads (8 warps). pre_enc is bf16.
__global__ __launch_bounds__(256) void attn_score(const float* __restrict__ gvec) {
    __shared__ float dp[512];
    __shared__ float gv[512];
    int b = blockIdx.y;
    int t0 = blockIdx.x * 50;
    int tid = threadIdx.x;
    for (int a = tid; a < 512; a += 256) {
        float s = 0.f;
#pragma unroll
        for (int sp = 0; sp < KS; sp++) s += g_partd[sp * (BB * AA) + b * AA + a];
        dp[a] = s;
        gv[a] = gvec[a];
    }
    __syncthreads();
    int warp = tid >> 5, lane = tid & 31;
    for (int t = t0 + warp; t < t0 + 50; t += 8) {
        const uint4* pe = (const uint4*)&g_preenc_bf[((size_t)b * TT + t) * AA];
        float acc = 0.f;
#pragma unroll
        for (int g = 0; g < 2; g++) {
            int q = lane + 32 * g;       // uint4 index, covers a = 8q..8q+7
            uint4 v = pe[q];
            float vf[8];
            unp8(v, vf);
#pragma unroll
            for (int r = 0; r < 8; r++) {
                int a = 8 * q + r;
                acc += gv[a] * tanh_ap(vf[r] + dp[a]);
            }
        }
#pragma unroll
        for (int off = 16; off; off >>= 1) acc += __shfl_xor_sync(0xffffffffu, acc, off);
        if (lane == 0) g_escore[b * TT + t] = acc;
    }
}

// ---------------- softmax + build x0 (ey | zero att_c slot | z0) ----------------
__global__ __launch_bounds__(256) void softmax_build(const int* __restrict__ hlens, int l) {
    __shared__ float red[256];
    int b = blockIdx.x, tid = threadIdx.x;
    int hlen = hlens[b];
    const float* e = &g_escore[b * TT];
    float mx = -1e30f;
    for (int t = tid; t < TT; t += 256)
        if (t < hlen) mx = fmaxf(mx, e[t]);
    red[tid] = mx; __syncthreads();
    for (int s = 128; s; s >>= 1) { if (tid < s) red[tid] = fmaxf(red[tid], red[tid + s]); __syncthreads(); }
    mx = red[0]; __syncthreads();
    float sum = 0.f;
    for (int t = tid; t < TT; t += 256)
        if (t < hlen) sum += __expf(2.0f * (e[t] - mx));
    red[tid] = sum; __syncthreads();
    for (int s = 128; s; s >>= 1) { if (tid < s) red[tid] += red[tid + s]; __syncthreads(); }
    float inv = 1.0f / red[0];
    for (int t = tid; t < TT; t += 256)
        g_attw[b * TT + t] = (t < hlen) ? __expf(2.0f * (e[t] - mx)) * inv : 0.f;
    // build x0: [0,1024)=ey_l ; [1024,1536)=0 (att_c accumulated by atomics) ; [1536,2560)=z0
    const float* ey = &g_eys[((size_t)b * LL + l) * DD];
    for (int i = tid; i < DD; i += 256) {
        g_x0[b * 2560 + i] = ey[i];
        g_x0[b * 2560 + 1536 + i] = g_z0[b * DD + i];
    }
    for (int i = tid; i < 512; i += 256) g_x0[b * 2560 + 1024 + i] = 0.f;
}

// ---------------- att_c accumulation (hs bf16): x0[b][1024+e] += sum_t w[b,t]*hs[b,t,e] ----------------
// grid 128 = b(16) x echunk(2) x tsplit(4), 128 threads; each thread handles 2 e's
__global__ __launch_bounds__(128) void attc_kernel(void) {
    __shared__ float w[200];
    int bx = blockIdx.x;
    int b = bx >> 3, ec = (bx >> 2) & 1, ts = bx & 3;
    int tid = threadIdx.x;
    int t0 = ts * 200;
    for (int i = tid; i < 200; i += 128) w[i] = g_attw[b * TT + t0 + i];
    __syncthreads();
    int e0 = ec * 256 + tid * 2;
    const unsigned int* hp = (const unsigned int*)&g_hs_bf[((size_t)b * TT + t0) * EE + e0];
    float acc0 = 0.f, acc1 = 0.f;
#pragma unroll 4
    for (int tt = 0; tt < 200; tt++) {
        unsigned int v = hp[(size_t)tt * (EE / 2)];
        float lo = __uint_as_float(v << 16);
        float hi = __uint_as_float(v & 0xffff0000u);
        acc0 = fmaf(w[tt], lo, acc0);
        acc1 = fmaf(w[tt], hi, acc1);
    }
    atomicAdd(&g_x0[b * 2560 + 1024 + e0], acc0);
    atomicAdd(&g_x0[b * 2560 + 1024 + e0 + 1], acc1);
}

// ---------------- LSTM cells ----------------
__global__ __launch_bounds__(256) void cell0(void) {
    int u = blockIdx.x * 256 + threadIdx.x;   // 16*1024
    int b = u >> 10, d = u & 1023;
    float gi = g_b0[d], gf = g_b0[1024 + d], gg = g_b0[2048 + d], go = g_b0[3072 + d];
#pragma unroll
    for (int s = 0; s < KS; s++) {
        const float* p = &g_part0[(size_t)s * (BB * 4096) + b * 4096];
        gi += p[d]; gf += p[1024 + d]; gg += p[2048 + d]; go += p[3072 + d];
    }
    float c = sigm(gf) * g_c0[u] + sigm(gi) * tanh_ap(gg);
    float h = sigm(go) * tanh_ap(c);
    g_c0[u] = c;
    g_z0[u] = h;
    g_x1[b * 2048 + d] = h;
    g_x1[b * 2048 + 1024 + d] = g_z1[u];
}
__global__ __launch_bounds__(256) void cell1(int l) {
    int u = blockIdx.x * 256 + threadIdx.x;
    int b = u >> 10, d = u & 1023;
    float gi = g_b1[d], gf = g_b1[1024 + d], gg = g_b1[2048 + d], go = g_b1[3072 + d];
#pragma unroll
    for (int s = 0; s < KS; s++) {
        const float* p = &g_part1[(size_t)s * (BB * 4096) + b * 4096];
        gi += p[d]; gf += p[1024 + d]; gg += p[2048 + d]; go += p[3072 + d];
    }
    float c = sigm(gf) * g_c1[u] + sigm(gi) * tanh_ap(gg);
    float h = sigm(go) * tanh_ap(c);
    g_c1[u] = c;
    g_z1[u] = h;
    g_zall[((size_t)b * LL + l) * DD + d] = h;
}

// ---------------- NLL per (b,l) row + final reduce ----------------
__global__ __launch_bounds__(256) void nll_kernel(const int* __restrict__ ys_pad) {
    __shared__ float red[256];
    int m = blockIdx.x, tid = threadIdx.x;
    int b = m / LL, l = m % LL;
    const float* row = &g_logits[(size_t)m * OO];
    float mx = -1e30f;
    for (int i = tid; i < OO; i += 256) mx = fmaxf(mx, row[i]);
    red[tid] = mx; __syncthreads();
    for (int s = 128; s; s >>= 1) { if (tid < s) red[tid] = fmaxf(red[tid], red[tid + s]); __syncthreads(); }
    mx = red[0]; __syncthreads();
    float sum = 0.f;
    for (int i = tid; i < OO; i += 256) sum += __expf(row[i] - mx);
    red[tid] = sum; __syncthreads();
    for (int s = 128; s; s >>= 1) { if (tid < s) red[tid] += red[tid + s]; __syncthreads(); }
    if (tid == 0) {
        int tgt = (l < 96) ? ys_pad[b * 96 + l] : SOSEOS;
        g_nll[m] = logf(red[0]) + mx - row[tgt];
    }
}
__global__ __launch_bounds__(256) void finalize(float* out) {
    __shared__ float red[256];
    int tid = threadIdx.x;
    float acc = 0.f;
    for (int i = tid; i < BB * LL; i += 256) acc += g_nll[i];
    red[tid] = acc; __syncthreads();
    for (int s = 128; s; s >>= 1) { if (tid < s) red[tid] += red[tid + s]; __syncthreads(); }
    if (tid == 0) out[0] = red[0] * (96.0f / (float)(BB * LL));
}

// ---------------- launch ----------------
extern "C" void kernel_launch(void* const* d_in, const int* in_sizes, int n_in,
                              void* d_out, int out_size) {
    const float* hs_pad = (const float*)d_in[0];
    const int*   hlens  = (const int*)d_in[1];
    const int*   ys_pad = (const int*)d_in[2];
    const float* embed  = (const float*)d_in[3];
    const float* W_ih0  = (const float*)d_in[4];
    const float* W_hh0  = (const float*)d_in[5];
    const float* b_ih0  = (const float*)d_in[6];
    const float* b_hh0  = (const float*)d_in[7];
    const float* W_ih1  = (const float*)d_in[8];
    const float* W_hh1  = (const float*)d_in[9];
    const float* b_ih1  = (const float*)d_in[10];
    const float* b_hh1  = (const float*)d_in[11];
    const float* W_enc  = (const float*)d_in[12];
    const float* b_enc  = (const float*)d_in[13];
    const float* W_dec  = (const float*)d_in[14];
    const float* gvec   = (const float*)d_in[15];
    const float* W_out  = (const float*)d_in[16];
    const float* b_out  = (const float*)d_in[17];
    float* out = (float*)d_out;

    pack_w0<<<(4096 * 2560 + 255) / 256, 256>>>(W_ih0, W_hh0);
    pack_w1<<<(4096 * 2048 + 255) / 256, 256>>>(W_ih1, W_hh1);
    pack_wd<<<(512 * 1024 + 255) / 256, 256>>>(W_dec);
    convert_hs<<<(BB * TT * EE + 255) / 256, 256>>>(hs_pad);
    prep_misc<<<(BB * LL * DD + 255) / 256, 256>>>(b_ih0, b_hh0, b_ih1, b_hh1, ys_pad, embed);

    // pre_enc = hs_pad @ W_enc^T + b_enc   (M=12800, N=512, K=512) -> bf16
    gemm_nt<1><<<dim3(4, 100), 256>>>(hs_pad, W_enc, b_enc, nullptr, g_preenc_bf, BB * TT, AA, EE);

    for (int l = 0; l < LL; l++) {
        // dec_proj = z0 @ W_dec^T  (N=512, K=1024)
        skinny_bf<<<dim3(4, KS), 128>>>(g_z0, g_WdT, g_partd, 1024, 512, 128);
        attn_score<<<dim3(16, 16), 256>>>(gvec);
        softmax_build<<<16, 256>>>(hlens, l);
        attc_kernel<<<128, 128>>>();
        // gates0 = x0 @ [W_ih0|W_hh0]^T  (N=4096, K=2560)
        skinny_bf<<<dim3(32, KS), 128>>>(g_x0, g_W0T, g_part0, 2560, 4096, 320);
        cell0<<<64, 256>>>();
        // gates1 = x1 @ [W_ih1|W_hh1]^T  (N=4096, K=2048)
        skinny_bf<<<dim3(32, KS), 128>>>(g_x1, g_W1T, g_part1, 2048, 4096, 256);
        cell1<<<64, 256>>>(l);
    }

    // logits = z_all @ W_out^T + b_out  (M=1552, N=5000, K=1024)
    gemm_nt<0><<<dim3(40, 13), 256>>>(g_zall, W_out, b_out, g_logits, nullptr, BB * LL, OO, DD);
    nll_kernel<<<BB * LL, 256>>>(ys_pad);
    finalize<<<1, 256>>>(out);
}

// round 3
// speedup vs baseline: 1.5216x; 1.0518x over previous
#include <cuda_runtime.h>
#include <cuda_bf16.h>
#include <math.h>
#include <stdint.h>

#define BB 16
#define TT 800
#define EE 512
#define DD 1024
#define AA 512
#define OO 5000
#define LL 97          // olength = LMAX + 1
#define KS 8           // k-split for skinny gemms
#define SOSEOS 4999

// ---------------- scratch (static __device__, no allocs) ----------------
__device__ __align__(16) unsigned short g_preenc_bf[BB * TT * AA];   // 13MB
__device__ __align__(16) unsigned short g_hs_bf[BB * TT * EE];       // 13MB
__device__ __align__(16) unsigned short g_W0T[2560 * 4096];          // 20MB bf16 packed k8-interleaved
__device__ __align__(16) unsigned short g_W1T[2048 * 4096];          // 16MB
__device__ __align__(16) unsigned short g_WdT[1024 * 512];           // 1MB
__device__ float g_b0[4096];
__device__ float g_b1[4096];
__device__ float g_eys[BB * LL * DD];
__device__ float g_z0[BB * DD], g_c0[BB * DD], g_z1[BB * DD], g_c1[BB * DD];
__device__ float g_x0[BB * 2560];                   // [ey | att_c | z0]
__device__ float g_x1[BB * 2048];                   // [z0_new | z1_old]
__device__ float g_escore[BB * TT];
__device__ float g_attw[BB * TT];
__device__ float g_partd[KS * BB * AA];
__device__ float g_part0[KS * BB * 4096];
__device__ float g_part1[KS * BB * 4096];
__device__ float g_zall[BB * LL * DD];
__device__ float g_logits[(size_t)BB * LL * OO];    // 31MB
__device__ float g_nll[BB * LL];

// ---------------- helpers ----------------
__device__ __forceinline__ float tanh_ap(float x) {
    float y;
    asm("tanh.approx.f32 %0, %1;" : "=f"(y) : "f"(x));
    return y;
}
__device__ __forceinline__ float sigm(float x) { return 1.0f / (1.0f + __expf(-x)); }
__device__ __forceinline__ unsigned short f2bf(float v) {
    return __bfloat16_as_ushort(__float2bfloat16_rn(v));
}
// unpack 8 bf16 (one uint4) to 8 floats: bf16 == high half of fp32
__device__ __forceinline__ void unp8(uint4 w, float* f) {
    f[0] = __uint_as_float(w.x << 16); f[1] = __uint_as_float(w.x & 0xffff0000u);
    f[2] = __uint_as_float(w.y << 16); f[3] = __uint_as_float(w.y & 0xffff0000u);
    f[4] = __uint_as_float(w.z << 16); f[5] = __uint_as_float(w.z & 0xffff0000u);
    f[6] = __uint_as_float(w.w << 16); f[7] = __uint_as_float(w.w & 0xffff0000u);
}

// ---------------- prep: pack weights bf16, k-major 8-interleaved ----------------
// layout: W*T[(k>>3)*(N*8) + j*8 + (k&7)]  -> uint4 load at ((k>>3)*N + j)
__global__ void pack_w0(const float* __restrict__ Wih0, const float* __restrict__ Whh0) {
    int idx = blockIdx.x * 256 + threadIdx.x;
    if (idx >= 4096 * 2560) return;
    int j = idx / 2560, k = idx % 2560;
    float v = (k < 1536) ? Wih0[j * 1536 + k] : Whh0[j * 1024 + (k - 1536)];
    g_W0T[(size_t)(k >> 3) * 32768 + j * 8 + (k & 7)] = f2bf(v);
}
__global__ void pack_w1(const float* __restrict__ Wih1, const float* __restrict__ Whh1) {
    int idx = blockIdx.x * 256 + threadIdx.x;
    if (idx >= 4096 * 2048) return;
    int j = idx / 2048, k = idx % 2048;
    float v = (k < 1024) ? Wih1[j * 1024 + k] : Whh1[j * 1024 + (k - 1024)];
    g_W1T[(size_t)(k >> 3) * 32768 + j * 8 + (k & 7)] = f2bf(v);
}
__global__ void pack_wd(const float* __restrict__ Wdec) {
    int idx = blockIdx.x * 256 + threadIdx.x;
    if (idx >= 512 * 1024) return;
    int j = idx / 1024, k = idx % 1024;
    g_WdT[(k >> 3) * 4096 + j * 8 + (k & 7)] = f2bf(Wdec[j * 1024 + k]);
}
__global__ void convert_hs(const float* __restrict__ hs) {
    int idx = blockIdx.x * 256 + threadIdx.x;
    if (idx < BB * TT * EE) g_hs_bf[idx] = f2bf(hs[idx]);
}
__global__ void prep_misc(const float* __restrict__ bih0, const float* __restrict__ bhh0,
                          const float* __restrict__ bih1, const float* __restrict__ bhh1,
                          const int* __restrict__ ys_pad, const float* __restrict__ embed) {
    int idx = blockIdx.x * 256 + threadIdx.x;
    if (idx < 4096) {
        g_b0[idx] = bih0[idx] + bhh0[idx];
        g_b1[idx] = bih1[idx] + bhh1[idx];
    }
    if (idx < BB * DD) {
        g_z0[idx] = 0.f; g_c0[idx] = 0.f; g_z1[idx] = 0.f; g_c1[idx] = 0.f;
    }
    if (idx < BB * LL * DD) {
        int m = idx >> 10;     // row (b,l)
        int d = idx & 1023;
        int b = m / LL, l = m % LL;
        int tok = (l == 0) ? SOSEOS : ys_pad[b * 96 + l - 1];
        g_eys[idx] = embed[(size_t)tok * DD + d];
    }
}

// ---------------- generic NT GEMM: C[M,N] = A[M,K] * B[N,K]^T + bias[n] ----------------
// 128x128 tile, BK=8, 256 threads, 8x8 per thread. STORE_BF=0 -> fp32 C, 1 -> bf16 C.
template <int STORE_BF>
__global__ __launch_bounds__(256) void gemm_nt(const float* __restrict__ A,
                                               const float* __restrict__ Bm,
                                               const float* __restrict__ bias,
                                               float* __restrict__ C,
                                               unsigned short* __restrict__ Cbf,
                                               int M, int N, int K) {
    __shared__ float As[8][128];
    __shared__ float Bs[8][128];
    int tid = threadIdx.x;
    int m0 = blockIdx.y * 128, n0 = blockIdx.x * 128;
    int lr = tid >> 1;            // 0..127
    int lk = (tid & 1) * 4;       // 0 or 4
    int tx = tid & 15, ty = tid >> 4;
    float acc[8][8];
#pragma unroll
    for (int i = 0; i < 8; i++)
#pragma unroll
        for (int j = 0; j < 8; j++) acc[i][j] = 0.f;

    for (int k0 = 0; k0 < K; k0 += 8) {
        float4 av = make_float4(0.f, 0.f, 0.f, 0.f);
        float4 bv = make_float4(0.f, 0.f, 0.f, 0.f);
        if (m0 + lr < M) av = *(const float4*)&A[(size_t)(m0 + lr) * K + k0 + lk];
        if (n0 + lr < N) bv = *(const float4*)&Bm[(size_t)(n0 + lr) * K + k0 + lk];
        __syncthreads();
        As[lk + 0][lr] = av.x; As[lk + 1][lr] = av.y; As[lk + 2][lr] = av.z; As[lk + 3][lr] = av.w;
        Bs[lk + 0][lr] = bv.x; Bs[lk + 1][lr] = bv.y; Bs[lk + 2][lr] = bv.z; Bs[lk + 3][lr] = bv.w;
        __syncthreads();
#pragma unroll
        for (int kk = 0; kk < 8; kk++) {
            float a[8], b[8];
            *(float4*)(a)     = *(const float4*)&As[kk][ty * 8];
            *(float4*)(a + 4) = *(const float4*)&As[kk][ty * 8 + 4];
            *(float4*)(b)     = *(const float4*)&Bs[kk][tx * 8];
            *(float4*)(b + 4) = *(const float4*)&Bs[kk][tx * 8 + 4];
#pragma unroll
            for (int i = 0; i < 8; i++)
#pragma unroll
                for (int j = 0; j < 8; j++) acc[i][j] += a[i] * b[j];
        }
    }
#pragma unroll
    for (int i = 0; i < 8; i++) {
        int m = m0 + ty * 8 + i;
        if (m >= M) continue;
#pragma unroll
        for (int j = 0; j < 8; j++) {
            int n = n0 + tx * 8 + j;
            if (n < N) {
                float v = acc[i][j] + bias[n];
                if (STORE_BF) Cbf[(size_t)m * N + n] = f2bf(v);
                else          C[(size_t)m * N + n] = v;
            }
        }
    }
}

// ---------------- skinny GEMM (bf16 weights): part[s][b][j] = sum_k x[b][k]*W[j][k] ----------------
// WT packed k-major 8-interleaved bf16. grid (N/128, KS), 128 threads.
__global__ __launch_bounds__(128) void skinny_bf(const float* __restrict__ x,
                                                 const unsigned short* __restrict__ WT,
                                                 float* __restrict__ part,
                                                 int K, int N, int kchunk) {
    __shared__ float xs[16 * 320];
    int j = blockIdx.x * 128 + threadIdx.x;
    int kc = blockIdx.y * kchunk;
    for (int i = threadIdx.x; i < 16 * kchunk; i += 128) {
        int b = i / kchunk, kk = i - b * kchunk;
        xs[i] = x[b * K + kc + kk];
    }
    __syncthreads();
    float acc[16];
#pragma unroll
    for (int b = 0; b < 16; b++) acc[b] = 0.f;

    const uint4* wp = (const uint4*)WT;
#pragma unroll 4
    for (int kk = 0; kk < kchunk; kk += 8) {
        uint4 w = wp[(size_t)((kc + kk) >> 3) * N + j];
        float wf[8];
        unp8(w, wf);
#pragma unroll
        for (int b = 0; b < 16; b++) {
            float4 xa = *(const float4*)&xs[b * kchunk + kk];
            float4 xb = *(const float4*)&xs[b * kchunk + kk + 4];
            float s = acc[b];
            s = fmaf(wf[0], xa.x, s); s = fmaf(wf[1], xa.y, s);
            s = fmaf(wf[2], xa.z, s); s = fmaf(wf[3], xa.w, s);
            s = fmaf(wf[4], xb.x, s); s = fmaf(wf[5], xb.y, s);
            s = fmaf(wf[6], xb.z, s); s = fmaf(wf[7], xb.w, s);
            acc[b] = s;
        }
    }
    float* po = part + (size_t)blockIdx.y * (16 * N);
#pragma unroll
    for (int b = 0; b < 16; b++) po[b * N + j] = acc[b];
}

// ---------------- attention score: e[b,t] = sum_a g[a]*tanh(pre_enc + dec_proj) ----------------
// grid (16 t-chunks of 50, 16 b), 256 threads (8 warps). pre_enc is bf16.
__global__ __launch_bounds__(256) void attn_score(const float* __restrict__ gvec) {
    __shared__ float dp[512];
    __shared__ float gv[512];
    int b = blockIdx.y;
    int t0 = blockIdx.x * 50;
    int tid = threadIdx.x;
    for (int a = tid; a < 512; a += 256) {
        float s = 0.f;
#pragma unroll
        for (int sp = 0; sp < KS; sp++) s += g_partd[sp * (BB * AA) + b * AA + a];
        dp[a] = s;
        gv[a] = gvec[a];
    }
    __syncthreads();
    int warp = tid >> 5, lane = tid & 31;
    for (int t = t0 + warp; t < t0 + 50; t += 8) {
        const uint4* pe = (const uint4*)&g_preenc_bf[((size_t)b * TT + t) * AA];
        float acc = 0.f;
#pragma unroll
        for (int g = 0; g < 2; g++) {
            int q = lane + 32 * g;       // uint4 index, covers a = 8q..8q+7
            uint4 v = pe[q];
            float vf[8];
            unp8(v, vf);
#pragma unroll
            for (int r = 0; r < 8; r++) {
                int a = 8 * q + r;
                acc += gv[a] * tanh_ap(vf[r] + dp[a]);
            }
        }
#pragma unroll
        for (int off = 16; off; off >>= 1) acc += __shfl_xor_sync(0xffffffffu, acc, off);
        if (lane == 0) g_escore[b * TT + t] = acc;
    }
}

// ---------------- softmax + build x0 (ey | zero att_c slot | z0) ----------------
__global__ __launch_bounds__(256) void softmax_build(const int* __restrict__ hlens, int l) {
    __shared__ float red[256];
    int b = blockIdx.x, tid = threadIdx.x;
    int hlen = hlens[b];
    const float* e = &g_escore[b * TT];
    float mx = -1e30f;
    for (int t = tid; t < TT; t += 256)
        if (t < hlen) mx = fmaxf(mx, e[t]);
    red[tid] = mx; __syncthreads();
    for (int s = 128; s; s >>= 1) { if (tid < s) red[tid] = fmaxf(red[tid], red[tid + s]); __syncthreads(); }
    mx = red[0]; __syncthreads();
    float sum = 0.f;
    for (int t = tid; t < TT; t += 256)
        if (t < hlen) sum += __expf(2.0f * (e[t] - mx));
    red[tid] = sum; __syncthreads();
    for (int s = 128; s; s >>= 1) { if (tid < s) red[tid] += red[tid + s]; __syncthreads(); }
    float inv = 1.0f / red[0];
    for (int t = tid; t < TT; t += 256)
        g_attw[b * TT + t] = (t < hlen) ? __expf(2.0f * (e[t] - mx)) * inv : 0.f;
    // build x0: [0,1024)=ey_l ; [1024,1536)=0 (att_c accumulated by atomics) ; [1536,2560)=z0
    const float* ey = &g_eys[((size_t)b * LL + l) * DD];
    for (int i = tid; i < DD; i += 256) {
        g_x0[b * 2560 + i] = ey[i];
        g_x0[b * 2560 + 1536 + i] = g_z0[b * DD + i];
    }
    for (int i = tid; i < 512; i += 256) g_x0[b * 2560 + 1024 + i] = 0.f;
}

// ---------------- att_c accumulation (hs bf16): x0[b][1024+e] += sum_t w[b,t]*hs[b,t,e] ----------------
// grid 128 = b(16) x echunk(2) x tsplit(4), 128 threads; each thread handles 2 e's
__global__ __launch_bounds__(128) void attc_kernel(void) {
    __shared__ float w[200];
    int bx = blockIdx.x;
    int b = bx >> 3, ec = (bx >> 2) & 1, ts = bx & 3;
    int tid = threadIdx.x;
    int t0 = ts * 200;
    for (int i = tid; i < 200; i += 128) w[i] = g_attw[b * TT + t0 + i];
    __syncthreads();
    int e0 = ec * 256 + tid * 2;
    const unsigned int* hp = (const unsigned int*)&g_hs_bf[((size_t)b * TT + t0) * EE + e0];
    float acc0 = 0.f, acc1 = 0.f;
#pragma unroll 4
    for (int tt = 0; tt < 200; tt++) {
        unsigned int v = hp[(size_t)tt * (EE / 2)];
        float lo = __uint_as_float(v << 16);
        float hi = __uint_as_float(v & 0xffff0000u);
        acc0 = fmaf(w[tt], lo, acc0);
        acc1 = fmaf(w[tt], hi, acc1);
    }
    atomicAdd(&g_x0[b * 2560 + 1024 + e0], acc0);
    atomicAdd(&g_x0[b * 2560 + 1024 + e0 + 1], acc1);
}

// ---------------- LSTM cells ----------------
__global__ __launch_bounds__(256) void cell0(void) {
    int u = blockIdx.x * 256 + threadIdx.x;   // 16*1024
    int b = u >> 10, d = u & 1023;
    float gi = g_b0[d], gf = g_b0[1024 + d], gg = g_b0[2048 + d], go = g_b0[3072 + d];
#pragma unroll
    for (int s = 0; s < KS; s++) {
        const float* p = &g_part0[(size_t)s * (BB * 4096) + b * 4096];
        gi += p[d]; gf += p[1024 + d]; gg += p[2048 + d]; go += p[3072 + d];
    }
    float c = sigm(gf) * g_c0[u] + sigm(gi) * tanh_ap(gg);
    float h = sigm(go) * tanh_ap(c);
    g_c0[u] = c;
    g_z0[u] = h;
    g_x1[b * 2048 + d] = h;
    g_x1[b * 2048 + 1024 + d] = g_z1[u];
}
__global__ __launch_bounds__(256) void cell1(int l) {
    int u = blockIdx.x * 256 + threadIdx.x;
    int b = u >> 10, d = u & 1023;
    float gi = g_b1[d], gf = g_b1[1024 + d], gg = g_b1[2048 + d], go = g_b1[3072 + d];
#pragma unroll
    for (int s = 0; s < KS; s++) {
        const float* p = &g_part1[(size_t)s * (BB * 4096) + b * 4096];
        gi += p[d]; gf += p[1024 + d]; gg += p[2048 + d]; go += p[3072 + d];
    }
    float c = sigm(gf) * g_c1[u] + sigm(gi) * tanh_ap(gg);
    float h = sigm(go) * tanh_ap(c);
    g_c1[u] = c;
    g_z1[u] = h;
    g_zall[((size_t)b * LL + l) * DD + d] = h;
}

// ---------------- NLL per (b,l) row + final reduce ----------------
__global__ __launch_bounds__(256) void nll_kernel(const int* __restrict__ ys_pad) {
    __shared__ float red[256];
    int m = blockIdx.x, tid = threadIdx.x;
    int b = m / LL, l = m % LL;
    const float* row = &g_logits[(size_t)m * OO];
    float mx = -1e30f;
    for (int i = tid; i < OO; i += 256) mx = fmaxf(mx, row[i]);
    red[tid] = mx; __syncthreads();
    for (int s = 128; s; s >>= 1) { if (tid < s) red[tid] = fmaxf(red[tid], red[tid + s]); __syncthreads(); }
    mx = red[0]; __syncthreads();
    float sum = 0.f;
    for (int i = tid; i < OO; i += 256) sum += __expf(row[i] - mx);
    red[tid] = sum; __syncthreads();
    for (int s = 128; s; s >>= 1) { if (tid < s) red[tid] += red[tid + s]; __syncthreads(); }
    if (tid == 0) {
        int tgt = (l < 96) ? ys_pad[b * 96 + l] : SOSEOS;
        g_nll[m] = logf(red[0]) + mx - row[tgt];
    }
}
__global__ __launch_bounds__(256) void finalize(float* out) {
    __shared__ float red[256];
    int tid = threadIdx.x;
    float acc = 0.f;
    for (int i = tid; i < BB * LL; i += 256) acc += g_nll[i];
    red[tid] = acc; __syncthreads();
    for (int s = 128; s; s >>= 1) { if (tid < s) red[tid] += red[tid + s]; __syncthreads(); }
    if (tid == 0) out[0] = red[0] * (96.0f / (float)(BB * LL));
}

// ---------------- launch ----------------
extern "C" void kernel_launch(void* const* d_in, const int* in_sizes, int n_in,
                              void* d_out, int out_size) {
    const float* hs_pad = (const float*)d_in[0];
    const int*   hlens  = (const int*)d_in[1];
    const int*   ys_pad = (const int*)d_in[2];
    const float* embed  = (const float*)d_in[3];
    const float* W_ih0  = (const float*)d_in[4];
    const float* W_hh0  = (const float*)d_in[5];
    const float* b_ih0  = (const float*)d_in[6];
    const float* b_hh0  = (const float*)d_in[7];
    const float* W_ih1  = (const float*)d_in[8];
    const float* W_hh1  = (const float*)d_in[9];
    const float* b_ih1  = (const float*)d_in[10];
    const float* b_hh1  = (const float*)d_in[11];
    const float* W_enc  = (const float*)d_in[12];
    const float* b_enc  = (const float*)d_in[13];
    const float* W_dec  = (const float*)d_in[14];
    const float* gvec   = (const float*)d_in[15];
    const float* W_out  = (const float*)d_in[16];
    const float* b_out  = (const float*)d_in[17];
    float* out = (float*)d_out;

    pack_w0<<<(4096 * 2560 + 255) / 256, 256>>>(W_ih0, W_hh0);
    pack_w1<<<(4096 * 2048 + 255) / 256, 256>>>(W_ih1, W_hh1);
    pack_wd<<<(512 * 1024 + 255) / 256, 256>>>(W_dec);
    convert_hs<<<(BB * TT * EE + 255) / 256, 256>>>(hs_pad);
    prep_misc<<<(BB * LL * DD + 255) / 256, 256>>>(b_ih0, b_hh0, b_ih1, b_hh1, ys_pad, embed);

    // pre_enc = hs_pad @ W_enc^T + b_enc   (M=12800, N=512, K=512) -> bf16
    gemm_nt<1><<<dim3(4, 100), 256>>>(hs_pad, W_enc, b_enc, nullptr, g_preenc_bf, BB * TT, AA, EE);

    for (int l = 0; l < LL; l++) {
        // dec_proj = z0 @ W_dec^T  (N=512, K=1024)
        skinny_bf<<<dim3(4, KS), 128>>>(g_z0, g_WdT, g_partd, 1024, 512, 128);
        attn_score<<<dim3(16, 16), 256>>>(gvec);
        softmax_build<<<16, 256>>>(hlens, l);
        attc_kernel<<<128, 128>>>();
        // gates0 = x0 @ [W_ih0|W_hh0]^T  (N=4096, K=2560)
        skinny_bf<<<dim3(32, KS), 128>>>(g_x0, g_W0T, g_part0, 2560, 4096, 320);
        cell0<<<64, 256>>>();
        // gates1 = x1 @ [W_ih1|W_hh1]^T  (N=4096, K=2048)
        skinny_bf<<<dim3(32, KS), 128>>>(g_x1, g_W1T, g_part1, 2048, 4096, 256);
        cell1<<<64, 256>>>(l);
    }

    // logits = z_all @ W_out^T + b_out  (M=1552, N=5000, K=1024)
    gemm_nt<0><<<dim3(40, 13), 256>>>(g_zall, W_out, b_out, g_logits, nullptr, BB * LL, OO, DD);
    nll_kernel<<<BB * LL, 256>>>(ys_pad);
    finalize<<<1, 256>>>(out);
}

// round 4
// speedup vs baseline: 4.2976x; 2.8244x over previous
#include <cuda_runtime.h>
#include <cuda_bf16.h>
#include <math.h>
#include <stdint.h>

#define BB 16
#define TT 800
#define EE 512
#define DD 1024
#define AA 512
#define OO 5000
#define LL 97
#define SOSEOS 4999
#define NBLK 148
#define NTH 256

// ---------------- scratch ----------------
__device__ __align__(16) unsigned short g_preenc_bf[BB * TT * AA];
__device__ __align__(16) unsigned short g_hs_bf[BB * TT * EE];
__device__ __align__(16) unsigned short g_W0P[2560 * 4096];
__device__ __align__(16) unsigned short g_W1P[2048 * 4096];
__device__ __align__(16) unsigned short g_WdP[1024 * 512];
__device__ float g_b0[4096], g_b1[4096];
__device__ float g_eys[BB * LL * DD];
__device__ float g_z0[BB * DD], g_c0[BB * DD], g_z1[BB * DD], g_c1[BB * DD];
__device__ float g_x0[BB * 2560];
__device__ float g_x1[BB * 2048];
__device__ float g_escore[BB * TT];
__device__ float g_partd[8 * BB * AA];
__device__ float g_part0[8 * BB * 4096];
__device__ float g_part1[8 * BB * 4096];
__device__ float g_zall[BB * LL * DD];
__device__ float g_logits[(size_t)BB * LL * OO];
__device__ float g_nll[BB * LL];
__device__ unsigned g_cnt;
__device__ unsigned g_gen;

// ---------------- helpers ----------------
__device__ __forceinline__ float tanh_ap(float x) {
    float y; asm("tanh.approx.f32 %0, %1;" : "=f"(y) : "f"(x)); return y;
}
__device__ __forceinline__ float sigm(float x) { return 1.0f / (1.0f + __expf(-x)); }
__device__ __forceinline__ unsigned short f2bf(float v) {
    return __bfloat16_as_ushort(__float2bfloat16_rn(v));
}
__device__ __forceinline__ void unp8(uint4 w, float* f) {
    f[0] = __uint_as_float(w.x << 16); f[1] = __uint_as_float(w.x & 0xffff0000u);
    f[2] = __uint_as_float(w.y << 16); f[3] = __uint_as_float(w.y & 0xffff0000u);
    f[4] = __uint_as_float(w.z << 16); f[5] = __uint_as_float(w.z & 0xffff0000u);
    f[6] = __uint_as_float(w.w << 16); f[7] = __uint_as_float(w.w & 0xffff0000u);
}

// device-wide barrier (all NBLK blocks co-resident, 1/SM)
__device__ __forceinline__ void gbar() {
    __syncthreads();
    __threadfence();                       // release + L1 flush
    if (threadIdx.x == 0) {
        unsigned seen = atomicAdd(&g_gen, 0u);
        unsigned my = atomicAdd(&g_cnt, 1u);
        if (my == NBLK - 1) {
            atomicExch(&g_cnt, 0u);
            __threadfence();
            atomicAdd(&g_gen, 1u);
        } else {
            while (atomicAdd(&g_gen, 0u) == seen) { __nanosleep(64); }
        }
        __threadfence();                   // acquire + L1 flush
    }
    __syncthreads();
}

// ---------------- prolog kernels ----------------
__global__ void pack_w0(const float* __restrict__ Wih0, const float* __restrict__ Whh0) {
    int idx = blockIdx.x * 256 + threadIdx.x;
    if (idx >= 4096 * 2560) return;
    int j = idx / 2560, k = idx % 2560;
    float v = (k < 1536) ? Wih0[j * 1536 + k] : Whh0[j * 1024 + (k - 1536)];
    g_W0P[(size_t)(k >> 3) * 32768 + j * 8 + (k & 7)] = f2bf(v);
}
__global__ void pack_w1(const float* __restrict__ Wih1, const float* __restrict__ Whh1) {
    int idx = blockIdx.x * 256 + threadIdx.x;
    if (idx >= 4096 * 2048) return;
    int j = idx / 2048, k = idx % 2048;
    float v = (k < 1024) ? Wih1[j * 1024 + k] : Whh1[j * 1024 + (k - 1024)];
    g_W1P[(size_t)(k >> 3) * 32768 + j * 8 + (k & 7)] = f2bf(v);
}
__global__ void pack_wd(const float* __restrict__ Wdec) {
    int idx = blockIdx.x * 256 + threadIdx.x;
    if (idx >= 512 * 1024) return;
    int j = idx / 1024, k = idx % 1024;
    g_WdP[(k >> 3) * 4096 + j * 8 + (k & 7)] = f2bf(Wdec[j * 1024 + k]);
}
__global__ void convert_hs(const float* __restrict__ hs) {
    int idx = blockIdx.x * 256 + threadIdx.x;
    if (idx < BB * TT * EE) g_hs_bf[idx] = f2bf(hs[idx]);
}
__global__ void prep_misc(const float* __restrict__ bih0, const float* __restrict__ bhh0,
                          const float* __restrict__ bih1, const float* __restrict__ bhh1,
                          const int* __restrict__ ys_pad, const float* __restrict__ embed) {
    int idx = blockIdx.x * 256 + threadIdx.x;
    if (idx < 4096) {
        g_b0[idx] = bih0[idx] + bhh0[idx];
        g_b1[idx] = bih1[idx] + bhh1[idx];
    }
    if (idx < BB * DD) { g_z0[idx] = 0.f; g_c0[idx] = 0.f; g_z1[idx] = 0.f; g_c1[idx] = 0.f; }
    if (idx < 8 * BB * AA) g_partd[idx] = 0.f;
    if (idx < BB * LL * DD) {
        int m = idx >> 10, d = idx & 1023;
        int b = m / LL, l = m % LL;
        int tok = (l == 0) ? SOSEOS : ys_pad[b * 96 + l - 1];
        g_eys[idx] = embed[(size_t)tok * DD + d];
    }
}

// ---------------- generic NT GEMM (pre_enc + logits) ----------------
template <int STORE_BF>
__global__ __launch_bounds__(256) void gemm_nt(const float* __restrict__ A,
                                               const float* __restrict__ Bm,
                                               const float* __restrict__ bias,
                                               float* __restrict__ C,
                                               unsigned short* __restrict__ Cbf,
                                               int M, int N, int K) {
    __shared__ float As[8][128];
    __shared__ float Bs[8][128];
    int tid = threadIdx.x;
    int m0 = blockIdx.y * 128, n0 = blockIdx.x * 128;
    int lr = tid >> 1, lk = (tid & 1) * 4;
    int tx = tid & 15, ty = tid >> 4;
    float acc[8][8];
#pragma unroll
    for (int i = 0; i < 8; i++)
#pragma unroll
        for (int j = 0; j < 8; j++) acc[i][j] = 0.f;
    for (int k0 = 0; k0 < K; k0 += 8) {
        float4 av = make_float4(0.f,0.f,0.f,0.f), bv = make_float4(0.f,0.f,0.f,0.f);
        if (m0 + lr < M) av = *(const float4*)&A[(size_t)(m0 + lr) * K + k0 + lk];
        if (n0 + lr < N) bv = *(const float4*)&Bm[(size_t)(n0 + lr) * K + k0 + lk];
        __syncthreads();
        As[lk+0][lr]=av.x; As[lk+1][lr]=av.y; As[lk+2][lr]=av.z; As[lk+3][lr]=av.w;
        Bs[lk+0][lr]=bv.x; Bs[lk+1][lr]=bv.y; Bs[lk+2][lr]=bv.z; Bs[lk+3][lr]=bv.w;
        __syncthreads();
#pragma unroll
        for (int kk = 0; kk < 8; kk++) {
            float a[8], b[8];
            *(float4*)(a)   = *(const float4*)&As[kk][ty*8];
            *(float4*)(a+4) = *(const float4*)&As[kk][ty*8+4];
            *(float4*)(b)   = *(const float4*)&Bs[kk][tx*8];
            *(float4*)(b+4) = *(const float4*)&Bs[kk][tx*8+4];
#pragma unroll
            for (int i = 0; i < 8; i++)
#pragma unroll
                for (int j = 0; j < 8; j++) acc[i][j] += a[i] * b[j];
        }
    }
#pragma unroll
    for (int i = 0; i < 8; i++) {
        int m = m0 + ty*8 + i;
        if (m >= M) continue;
#pragma unroll
        for (int j = 0; j < 8; j++) {
            int n = n0 + tx*8 + j;
            if (n < N) {
                float v = acc[i][j] + bias[n];
                if (STORE_BF) Cbf[(size_t)m * N + n] = f2bf(v);
                else          C[(size_t)m * N + n] = v;
            }
        }
    }
}

// ---------------- skinny GEMM phase body ----------------
__device__ __forceinline__ void skinny_phase(const float* __restrict__ x,
                                             const unsigned short* __restrict__ WP,
                                             float* __restrict__ part,
                                             int K, int N, int jg_count, int kchunk,
                                             int vb, float* xs) {
    int tid = threadIdx.x;
    int jg = vb % jg_count, ks = vb / jg_count;
    int kc = ks * kchunk;
    __syncthreads();
    for (int i = tid; i < 16 * kchunk; i += NTH) {
        int b = i / kchunk, kk = i - b * kchunk;
        xs[i] = x[b * K + kc + kk];
    }
    __syncthreads();
    int j = jg * 256 + tid;
    const uint4* wp = (const uint4*)WP;
    float acc[16];
#pragma unroll
    for (int b = 0; b < 16; b++) acc[b] = 0.f;
#pragma unroll 4
    for (int kk = 0; kk < kchunk; kk += 8) {
        uint4 w = wp[(size_t)((kc + kk) >> 3) * N + j];
        float wf[8]; unp8(w, wf);
#pragma unroll
        for (int b = 0; b < 16; b++) {
            const float* xr = &xs[b * kchunk + kk];
            float4 xa = *(const float4*)xr;
            float4 xb = *(const float4*)(xr + 4);
            float s = acc[b];
            s = fmaf(wf[0], xa.x, s); s = fmaf(wf[1], xa.y, s);
            s = fmaf(wf[2], xa.z, s); s = fmaf(wf[3], xa.w, s);
            s = fmaf(wf[4], xb.x, s); s = fmaf(wf[5], xb.y, s);
            s = fmaf(wf[6], xb.z, s); s = fmaf(wf[7], xb.w, s);
            acc[b] = s;
        }
    }
#pragma unroll
    for (int b = 0; b < 16; b++) part[(ks * 16 + b) * N + j] = acc[b];
}

// ---------------- persistent decoder loop ----------------
extern "C" __global__ void __launch_bounds__(NTH, 1)
decoder_loop(const int* __restrict__ hlens, const float* __restrict__ gvec) {
    __shared__ float xs[5120];
    __shared__ float s_w[800];
    __shared__ float s_red[8];
    __shared__ float s_bc[2];

    const int bid = blockIdx.x, tid = threadIdx.x;
    const int lane = tid & 31, wid = tid >> 5;

    for (int l = 0; l < LL; l++) {
        // ===== P1: attention scores  (256 vbs) =====
        for (int vb = bid; vb < 256; vb += NBLK) {
            int b = vb & 15, t0 = (vb >> 4) * 50;
            float* dp = xs;          // 512
            float* gv = xs + 512;    // 512
            __syncthreads();
            for (int a = tid; a < 512; a += NTH) {
                float s = 0.f;
#pragma unroll
                for (int sp = 0; sp < 8; sp++) s += g_partd[(sp * 16 + b) * 512 + a];
                dp[a] = s;
                gv[a] = gvec[a];
            }
            __syncthreads();
            const unsigned* pe0 = (const unsigned*)&g_preenc_bf[((size_t)b * TT) * AA];
            for (int t = t0 + wid; t < t0 + 50; t += 8) {
                const unsigned* pe = pe0 + (size_t)t * 256;
                float acc = 0.f;
#pragma unroll
                for (int p = 0; p < 8; p++) {
                    int q = lane + 32 * p;          // uint idx: a = 2q,2q+1
                    unsigned v = pe[q];
                    float lo = __uint_as_float(v << 16);
                    float hi = __uint_as_float(v & 0xffff0000u);
                    float2 d  = *(const float2*)&dp[2 * q];
                    float2 gq = *(const float2*)&gv[2 * q];
                    acc += gq.x * tanh_ap(lo + d.x);
                    acc += gq.y * tanh_ap(hi + d.y);
                }
#pragma unroll
                for (int o = 16; o; o >>= 1) acc += __shfl_xor_sync(~0u, acc, o);
                if (lane == 0) g_escore[b * TT + t] = acc;
            }
        }
        gbar();

        // ===== P2: softmax + att_c + x0 build  (32 vbs) =====
        for (int vb = bid; vb < 32; vb += NBLK) {
            int b = vb >> 1, ec = vb & 1;
            int hlen = hlens[b];
            const float* e = &g_escore[b * TT];
            __syncthreads();
            float mx = -1e30f;
            for (int t = tid; t < TT; t += NTH)
                if (t < hlen) mx = fmaxf(mx, e[t]);
#pragma unroll
            for (int o = 16; o; o >>= 1) mx = fmaxf(mx, __shfl_xor_sync(~0u, mx, o));
            if (lane == 0) s_red[wid] = mx;
            __syncthreads();
            if (tid == 0) { float m = s_red[0]; for (int i = 1; i < 8; i++) m = fmaxf(m, s_red[i]); s_bc[0] = m; }
            __syncthreads();
            mx = s_bc[0];
            float sum = 0.f;
            for (int t = tid; t < TT; t += NTH) {
                float w = (t < hlen) ? __expf(2.0f * (e[t] - mx)) : 0.f;
                s_w[t] = w;
                sum += w;
            }
#pragma unroll
            for (int o = 16; o; o >>= 1) sum += __shfl_xor_sync(~0u, sum, o);
            if (lane == 0) s_red[wid] = sum;
            __syncthreads();
            if (tid == 0) { float s = 0.f; for (int i = 0; i < 8; i++) s += s_red[i]; s_bc[1] = 1.0f / s; }
            __syncthreads();
            float inv = s_bc[1];
            for (int t = tid; t < TT; t += NTH) s_w[t] *= inv;
            __syncthreads();
            // att_c: 256-wide e chunk, 128 threads x 2 e (uint), full t range
            if (tid < 128) {
                int e0 = ec * 256 + tid * 2;
                const unsigned* hp = (const unsigned*)&g_hs_bf[((size_t)b * TT) * EE + e0];
                float a0 = 0.f, a1 = 0.f;
#pragma unroll 4
                for (int t = 0; t < TT; t++) {
                    unsigned v = hp[(size_t)t * 256];
                    float w = s_w[t];
                    a0 = fmaf(w, __uint_as_float(v << 16), a0);
                    a1 = fmaf(w, __uint_as_float(v & 0xffff0000u), a1);
                }
                g_x0[b * 2560 + 1024 + e0]     = a0;
                g_x0[b * 2560 + 1024 + e0 + 1] = a1;
            }
            // x0 [ey | . | z0] parts: vb copies 1024 of 32768
            for (int i = tid; i < 1024; i += NTH) {
                int j = vb * 1024 + i;
                int b2 = j >> 11, r = j & 2047;
                if (r < 1024) g_x0[b2 * 2560 + r] = g_eys[((size_t)b2 * LL + l) * DD + r];
                else          g_x0[b2 * 2560 + 1536 + (r - 1024)] = g_z0[b2 * DD + (r - 1024)];
            }
        }
        gbar();

        // ===== P3: gates0 (128 vbs: jg16 x ks8, kchunk 320) =====
        for (int vb = bid; vb < 128; vb += NBLK)
            skinny_phase(g_x0, g_W0P, g_part0, 2560, 4096, 16, 320, vb, xs);
        gbar();

        // ===== P4: cell0 + x1 build (64 vbs) =====
        for (int vb = bid; vb < 64; vb += NBLK) {
            int u = vb * NTH + tid;
            int b = u >> 10, d = u & 1023;
            float gi = g_b0[d], gf = g_b0[1024 + d], gg = g_b0[2048 + d], go = g_b0[3072 + d];
#pragma unroll
            for (int s = 0; s < 8; s++) {
                const float* p = &g_part0[(size_t)(s * 16 + b) * 4096];
                gi += p[d]; gf += p[1024 + d]; gg += p[2048 + d]; go += p[3072 + d];
            }
            float c = sigm(gf) * g_c0[u] + sigm(gi) * tanh_ap(gg);
            float h = sigm(go) * tanh_ap(c);
            g_c0[u] = c; g_z0[u] = h;
            g_x1[b * 2048 + d] = h;
            g_x1[b * 2048 + 1024 + d] = g_z1[u];
        }
        gbar();

        // ===== P5: gates1 (128 vbs) + dec_proj for next step (16 vbs) =====
        for (int vb = bid; vb < 144; vb += NBLK) {
            if (vb < 128) skinny_phase(g_x1, g_W1P, g_part1, 2048, 4096, 16, 256, vb, xs);
            else          skinny_phase(g_z0, g_WdP, g_partd, 1024, 512, 2, 128, vb - 128, xs);
        }
        gbar();

        // ===== P6: cell1 (64 vbs) =====
        for (int vb = bid; vb < 64; vb += NBLK) {
            int u = vb * NTH + tid;
            int b = u >> 10, d = u & 1023;
            float gi = g_b1[d], gf = g_b1[1024 + d], gg = g_b1[2048 + d], go = g_b1[3072 + d];
#pragma unroll
            for (int s = 0; s < 8; s++) {
                const float* p = &g_part1[(size_t)(s * 16 + b) * 4096];
                gi += p[d]; gf += p[1024 + d]; gg += p[2048 + d]; go += p[3072 + d];
            }
            float c = sigm(gf) * g_c1[u] + sigm(gi) * tanh_ap(gg);
            float h = sigm(go) * tanh_ap(c);
            g_c1[u] = c; g_z1[u] = h;
            g_zall[((size_t)b * LL + l) * DD + d] = h;
        }
        gbar();
    }
}

// ---------------- epilogue ----------------
__global__ __launch_bounds__(256) void nll_kernel(const int* __restrict__ ys_pad) {
    __shared__ float red[256];
    int m = blockIdx.x, tid = threadIdx.x;
    int b = m / LL, l = m % LL;
    const float* row = &g_logits[(size_t)m * OO];
    float mx = -1e30f;
    for (int i = tid; i < OO; i += 256) mx = fmaxf(mx, row[i]);
    red[tid] = mx; __syncthreads();
    for (int s = 128; s; s >>= 1) { if (tid < s) red[tid] = fmaxf(red[tid], red[tid + s]); __syncthreads(); }
    mx = red[0]; __syncthreads();
    float sum = 0.f;
    for (int i = tid; i < OO; i += 256) sum += __expf(row[i] - mx);
    red[tid] = sum; __syncthreads();
    for (int s = 128; s; s >>= 1) { if (tid < s) red[tid] += red[tid + s]; __syncthreads(); }
    if (tid == 0) {
        int tgt = (l < 96) ? ys_pad[b * 96 + l] : SOSEOS;
        g_nll[m] = logf(red[0]) + mx - row[tgt];
    }
}
__global__ __launch_bounds__(256) void finalize(float* out) {
    __shared__ float red[256];
    int tid = threadIdx.x;
    float acc = 0.f;
    for (int i = tid; i < BB * LL; i += 256) acc += g_nll[i];
    red[tid] = acc; __syncthreads();
    for (int s = 128; s; s >>= 1) { if (tid < s) red[tid] += red[tid + s]; __syncthreads(); }
    if (tid == 0) out[0] = red[0] * (96.0f / (float)(BB * LL));
}

// ---------------- launch ----------------
extern "C" void kernel_launch(void* const* d_in, const int* in_sizes, int n_in,
                              void* d_out, int out_size) {
    const float* hs_pad = (const float*)d_in[0];
    const int*   hlens  = (const int*)d_in[1];
    const int*   ys_pad = (const int*)d_in[2];
    const float* embed  = (const float*)d_in[3];
    const float* W_ih0  = (const float*)d_in[4];
    const float* W_hh0  = (const float*)d_in[5];
    const float* b_ih0  = (const float*)d_in[6];
    const float* b_hh0  = (const float*)d_in[7];
    const float* W_ih1  = (const float*)d_in[8];
    const float* W_hh1  = (const float*)d_in[9];
    const float* b_ih1  = (const float*)d_in[10];
    const float* b_hh1  = (const float*)d_in[11];
    const float* W_enc  = (const float*)d_in[12];
    const float* b_enc  = (const float*)d_in[13];
    const float* W_dec  = (const float*)d_in[14];
    const float* gvec   = (const float*)d_in[15];
    const float* W_out  = (const float*)d_in[16];
    const float* b_out  = (const float*)d_in[17];
    float* out = (float*)d_out;

    pack_w0<<<(4096 * 2560 + 255) / 256, 256>>>(W_ih0, W_hh0);
    pack_w1<<<(4096 * 2048 + 255) / 256, 256>>>(W_ih1, W_hh1);
    pack_wd<<<(512 * 1024 + 255) / 256, 256>>>(W_dec);
    convert_hs<<<(BB * TT * EE + 255) / 256, 256>>>(hs_pad);
    prep_misc<<<(BB * LL * DD + 255) / 256, 256>>>(b_ih0, b_hh0, b_ih1, b_hh1, ys_pad, embed);

    // pre_enc = hs_pad @ W_enc^T + b_enc -> bf16
    gemm_nt<1><<<dim3(4, 100), 256>>>(hs_pad, W_enc, b_enc, nullptr, g_preenc_bf, BB * TT, AA, EE);

    // the whole 97-step recurrent loop in ONE persistent kernel
    decoder_loop<<<NBLK, NTH>>>(hlens, gvec);

    // logits = z_all @ W_out^T + b_out
    gemm_nt<0><<<dim3(40, 13), 256>>>(g_zall, W_out, b_out, g_logits, nullptr, BB * LL, OO, DD);
    nll_kernel<<<BB * LL, 256>>>(ys_pad);
    finalize<<<1, 256>>>(out);
}

// round 5
// speedup vs baseline: 6.8595x; 1.5961x over previous
#include <cuda_runtime.h>
#include <cuda_bf16.h>
#include <math.h>
#include <stdint.h>

#define BB 16
#define TT 800
#define EE 512
#define DD 1024
#define AA 512
#define OO 5000
#define LL 97
#define SOSEOS 4999
#define NBLK 148
#define NTH 512

#define KS0 32
#define KC0 80
#define KS1 32
#define KC1 64
#define KSD 8
#define KCD 128

// ---------------- scratch ----------------
__device__ __align__(16) unsigned short g_preenc_bf[BB * TT * AA];
__device__ __align__(16) unsigned short g_hs_bf[BB * TT * EE];
__device__ __align__(16) unsigned short g_W0P[2560 * 4096];
__device__ __align__(16) unsigned short g_W1P[2048 * 4096];
__device__ __align__(16) unsigned short g_WdP[1024 * 512];
__device__ float g_b0[4096], g_b1[4096];
__device__ float g_eys[BB * LL * DD];
__device__ float g_z0[BB * DD], g_c0[BB * DD], g_z1[BB * DD], g_c1[BB * DD];
__device__ float g_x0[BB * 2560];
__device__ float g_x1[BB * 2048];
__device__ float g_escore[BB * TT];
__device__ float g_partd[KSD * BB * AA];
__device__ float g_part0[(size_t)KS0 * BB * 4096];
__device__ float g_part1[(size_t)KS1 * BB * 4096];
__device__ float g_zall[BB * LL * DD];
__device__ float g_logits[(size_t)BB * LL * OO];
__device__ float g_nll[BB * LL];
__device__ volatile unsigned g_arr[NBLK];
__device__ volatile unsigned g_rel;

// ---------------- helpers ----------------
__device__ __forceinline__ float tanh_ap(float x) {
    float y; asm("tanh.approx.f32 %0, %1;" : "=f"(y) : "f"(x)); return y;
}
__device__ __forceinline__ float sigm(float x) { return 1.0f / (1.0f + __expf(-x)); }
__device__ __forceinline__ unsigned short f2bf(float v) {
    return __bfloat16_as_ushort(__float2bfloat16_rn(v));
}
__device__ __forceinline__ unsigned long long dup2(unsigned w) {
    unsigned long long r; asm("mov.b64 %0, {%1, %1};" : "=l"(r) : "r"(w)); return r;
}
__device__ __forceinline__ void ffma2(unsigned long long& a, unsigned long long w,
                                      unsigned long long x) {
    asm("fma.rn.f32x2 %0, %1, %2, %3;" : "=l"(a) : "l"(w), "l"(x), "l"(a));
}

// device-wide barrier: parallel arrival flags + single release word
__device__ __forceinline__ void gbar(unsigned ep) {
    __syncthreads();
    if (threadIdx.x == 0) {
        __threadfence();
        g_arr[blockIdx.x] = ep;
    }
    if (blockIdx.x == 0) {
        if (threadIdx.x < NBLK) {
            while (g_arr[threadIdx.x] < ep) { }
        }
        __syncthreads();
        if (threadIdx.x == 0) {
            __threadfence();
            g_rel = ep;
        }
    }
    if (threadIdx.x == 0) {
        while (g_rel < ep) { }
        __threadfence();
    }
    __syncthreads();
}

// ---------------- prolog kernels ----------------
__global__ void pack_w0(const float* __restrict__ Wih0, const float* __restrict__ Whh0) {
    int idx = blockIdx.x * 256 + threadIdx.x;
    if (idx >= 4096 * 2560) return;
    int j = idx / 2560, k = idx % 2560;
    float v = (k < 1536) ? Wih0[j * 1536 + k] : Whh0[j * 1024 + (k - 1536)];
    g_W0P[(size_t)(k >> 3) * 32768 + j * 8 + (k & 7)] = f2bf(v);
}
__global__ void pack_w1(const float* __restrict__ Wih1, const float* __restrict__ Whh1) {
    int idx = blockIdx.x * 256 + threadIdx.x;
    if (idx >= 4096 * 2048) return;
    int j = idx / 2048, k = idx % 2048;
    float v = (k < 1024) ? Wih1[j * 1024 + k] : Whh1[j * 1024 + (k - 1024)];
    g_W1P[(size_t)(k >> 3) * 32768 + j * 8 + (k & 7)] = f2bf(v);
}
__global__ void pack_wd(const float* __restrict__ Wdec) {
    int idx = blockIdx.x * 256 + threadIdx.x;
    if (idx >= 512 * 1024) return;
    int j = idx / 1024, k = idx % 1024;
    g_WdP[(k >> 3) * 4096 + j * 8 + (k & 7)] = f2bf(Wdec[j * 1024 + k]);
}
__global__ void convert_hs(const float* __restrict__ hs) {
    int idx = blockIdx.x * 256 + threadIdx.x;
    if (idx < BB * TT * EE) g_hs_bf[idx] = f2bf(hs[idx]);
}
__global__ void prep_misc(const float* __restrict__ bih0, const float* __restrict__ bhh0,
                          const float* __restrict__ bih1, const float* __restrict__ bhh1,
                          const int* __restrict__ ys_pad, const float* __restrict__ embed) {
    int idx = blockIdx.x * 256 + threadIdx.x;
    if (idx < 4096) {
        g_b0[idx] = bih0[idx] + bhh0[idx];
        g_b1[idx] = bih1[idx] + bhh1[idx];
    }
    if (idx < BB * DD) { g_z0[idx] = 0.f; g_c0[idx] = 0.f; g_z1[idx] = 0.f; g_c1[idx] = 0.f; }
    if (idx < KSD * BB * AA) g_partd[idx] = 0.f;
    if (idx < NBLK) g_arr[idx] = 0u;
    if (idx == 0) g_rel = 0u;
    if (idx < BB * LL * DD) {
        int m = idx >> 10, d = idx & 1023;
        int b = m / LL, l = m % LL;
        int tok = (l == 0) ? SOSEOS : ys_pad[b * 96 + l - 1];
        g_eys[idx] = embed[(size_t)tok * DD + d];
    }
}

// ---------------- generic NT GEMM (pre_enc + logits) ----------------
template <int STORE_BF>
__global__ __launch_bounds__(256) void gemm_nt(const float* __restrict__ A,
                                               const float* __restrict__ Bm,
                                               const float* __restrict__ bias,
                                               float* __restrict__ C,
                                               unsigned short* __restrict__ Cbf,
                                               int M, int N, int K) {
    __shared__ float As[8][128];
    __shared__ float Bs[8][128];
    int tid = threadIdx.x;
    int m0 = blockIdx.y * 128, n0 = blockIdx.x * 128;
    int lr = tid >> 1, lk = (tid & 1) * 4;
    int tx = tid & 15, ty = tid >> 4;
    float acc[8][8];
#pragma unroll
    for (int i = 0; i < 8; i++)
#pragma unroll
        for (int j = 0; j < 8; j++) acc[i][j] = 0.f;
    for (int k0 = 0; k0 < K; k0 += 8) {
        float4 av = make_float4(0.f,0.f,0.f,0.f), bv = make_float4(0.f,0.f,0.f,0.f);
        if (m0 + lr < M) av = *(const float4*)&A[(size_t)(m0 + lr) * K + k0 + lk];
        if (n0 + lr < N) bv = *(const float4*)&Bm[(size_t)(n0 + lr) * K + k0 + lk];
        __syncthreads();
        As[lk+0][lr]=av.x; As[lk+1][lr]=av.y; As[lk+2][lr]=av.z; As[lk+3][lr]=av.w;
        Bs[lk+0][lr]=bv.x; Bs[lk+1][lr]=bv.y; Bs[lk+2][lr]=bv.z; Bs[lk+3][lr]=bv.w;
        __syncthreads();
#pragma unroll
        for (int kk = 0; kk < 8; kk++) {
            float a[8], b[8];
            *(float4*)(a)   = *(const float4*)&As[kk][ty*8];
            *(float4*)(a+4) = *(const float4*)&As[kk][ty*8+4];
            *(float4*)(b)   = *(const float4*)&Bs[kk][tx*8];
            *(float4*)(b+4) = *(const float4*)&Bs[kk][tx*8+4];
#pragma unroll
            for (int i = 0; i < 8; i++)
#pragma unroll
                for (int j = 0; j < 8; j++) acc[i][j] += a[i] * b[j];
        }
    }
#pragma unroll
    for (int i = 0; i < 8; i++) {
        int m = m0 + ty*8 + i;
        if (m >= M) continue;
#pragma unroll
        for (int j = 0; j < 8; j++) {
            int n = n0 + tx*8 + j;
            if (n < N) {
                float v = acc[i][j] + bias[n];
                if (STORE_BF) Cbf[(size_t)m * N + n] = f2bf(v);
                else          C[(size_t)m * N + n] = v;
            }
        }
    }
}

// ---------------- FFMA2 skinny GEMM phase ----------------
// part[(ks*16+b)*N + j] = sum_{k in chunk} x[b][kc+k] * W[j][kc+k]
// J2 = output columns per thread. xs layout: [k][16 b], row stride 20 floats.
template <int J2>
__device__ __forceinline__ void skinny_ffma2(const float* __restrict__ x,
        const unsigned short* __restrict__ WP, float* __restrict__ part,
        int K, int N, int kchunk, int jg, int ks, float* xs) {
    int tid = threadIdx.x;
    int kc = ks * kchunk;
    __syncthreads();
    for (int i = tid; i < 16 * kchunk; i += NTH) {
        int b = i / kchunk, k = i - b * kchunk;
        xs[k * 20 + b] = x[b * K + kc + k];
    }
    __syncthreads();
    int j0 = jg * (NTH * J2) + tid;
    const uint4* wp = (const uint4*)WP;
    unsigned long long acc[J2][8];
#pragma unroll
    for (int jj = 0; jj < J2; jj++)
#pragma unroll
        for (int bp = 0; bp < 8; bp++) acc[jj][bp] = 0ull;

    for (int kk = 0; kk < kchunk; kk += 8) {
        size_t wrow = (size_t)((kc + kk) >> 3) * N;
        uint4 wv[J2];
#pragma unroll
        for (int jj = 0; jj < J2; jj++) wv[jj] = wp[wrow + j0 + jj * NTH];
#pragma unroll
        for (int r = 0; r < 8; r++) {
            const ulonglong2* xr = (const ulonglong2*)&xs[(kk + r) * 20];
            ulonglong2 xA = xr[0], xB = xr[1];
#pragma unroll
            for (int jj = 0; jj < J2; jj++) {
                unsigned comp = ((const unsigned*)&wv[jj])[r >> 1];
                unsigned wb = (r & 1) ? (comp & 0xffff0000u) : (comp << 16);
                unsigned long long w2 = dup2(wb);
                ffma2(acc[jj][0], w2, xA.x);
                ffma2(acc[jj][1], w2, xA.y);
                ffma2(acc[jj][2], w2, xB.x);
                ffma2(acc[jj][3], w2, xB.y);
            }
            ulonglong2 xC = xr[2], xD = xr[3];
#pragma unroll
            for (int jj = 0; jj < J2; jj++) {
                unsigned comp = ((const unsigned*)&wv[jj])[r >> 1];
                unsigned wb = (r & 1) ? (comp & 0xffff0000u) : (comp << 16);
                unsigned long long w2 = dup2(wb);
                ffma2(acc[jj][4], w2, xC.x);
                ffma2(acc[jj][5], w2, xC.y);
                ffma2(acc[jj][6], w2, xD.x);
                ffma2(acc[jj][7], w2, xD.y);
            }
        }
    }
#pragma unroll
    for (int jj = 0; jj < J2; jj++) {
        int j = j0 + jj * NTH;
        float* po = part + (size_t)(ks * 16) * N + j;
#pragma unroll
        for (int bp = 0; bp < 8; bp++) {
            unsigned lo, hi;
            asm("mov.b64 {%0, %1}, %2;" : "=r"(lo), "=r"(hi) : "l"(acc[jj][bp]));
            po[(size_t)(2 * bp) * N]     = __uint_as_float(lo);
            po[(size_t)(2 * bp + 1) * N] = __uint_as_float(hi);
        }
    }
}

// ---------------- cell helpers ----------------
__device__ __forceinline__ void do_cell0(int u) {
    int b = u >> 10, d = u & 1023;
    float gi = g_b0[d], gf = g_b0[1024 + d], gg = g_b0[2048 + d], go = g_b0[3072 + d];
#pragma unroll 8
    for (int s = 0; s < KS0; s++) {
        const float* p = &g_part0[(size_t)(s * 16 + b) * 4096];
        gi += p[d]; gf += p[1024 + d]; gg += p[2048 + d]; go += p[3072 + d];
    }
    float c = sigm(gf) * g_c0[u] + sigm(gi) * tanh_ap(gg);
    float h = sigm(go) * tanh_ap(c);
    g_c0[u] = c; g_z0[u] = h;
    g_x1[b * 2048 + d] = h;
    g_x1[b * 2048 + 1024 + d] = g_z1[u];
}
__device__ __forceinline__ void do_cell1(int u, int l) {
    int b = u >> 10, d = u & 1023;
    float gi = g_b1[d], gf = g_b1[1024 + d], gg = g_b1[2048 + d], go = g_b1[3072 + d];
#pragma unroll 8
    for (int s = 0; s < KS1; s++) {
        const float* p = &g_part1[(size_t)(s * 16 + b) * 4096];
        gi += p[d]; gf += p[1024 + d]; gg += p[2048 + d]; go += p[3072 + d];
    }
    float c = sigm(gf) * g_c1[u] + sigm(gi) * tanh_ap(gg);
    float h = sigm(go) * tanh_ap(c);
    g_c1[u] = c; g_z1[u] = h;
    g_zall[((size_t)b * LL + l) * DD + d] = h;
}

// ---------------- persistent decoder loop ----------------
extern "C" __global__ void __launch_bounds__(NTH, 1)
decoder_loop(const int* __restrict__ hlens, const float* __restrict__ gvec) {
    __shared__ __align__(16) float xs[2944];
    __shared__ float s_red[16];
    __shared__ float s_bc[2];
    const int bid = blockIdx.x, tid = threadIdx.x;
    const int lane = tid & 31, wid = tid >> 5;
    unsigned ep = 0;

    for (int l = 0; l < LL; l++) {
        // ===== P1: e[b,t] = sum_a gvec[a] * tanh(pre_enc[b,t,a] + dp[b,a]) =====
        {
            int r0 = bid * 86 + min(bid, 72);
            int nr = 86 + (bid < 72 ? 1 : 0);
            int b0 = r0 / 800;
            float* dp = xs;            // 1024 (two b slices)
            float* gv = xs + 1024;     // 512
            for (int a = tid; a < 512; a += NTH) {
                float s0 = 0.f, s1 = 0.f;
#pragma unroll
                for (int s = 0; s < KSD; s++) {
                    s0 += g_partd[(s * 16 + b0) * 512 + a];
                    s1 += (b0 + 1 < 16) ? g_partd[(s * 16 + b0 + 1) * 512 + a] : 0.f;
                }
                dp[a] = s0; dp[512 + a] = s1;
                gv[a] = gvec[a];
            }
            __syncthreads();
            for (int r = r0 + wid; r < r0 + nr; r += 16) {
                int b = r / 800;
                const unsigned* pe = (const unsigned*)g_preenc_bf + (size_t)r * 256;
                const float* dpb = dp + (b - b0) * 512;
                float acc = 0.f;
#pragma unroll
                for (int p = 0; p < 8; p++) {
                    int q = lane + 32 * p;
                    unsigned v = pe[q];
                    float lo = __uint_as_float(v << 16);
                    float hi = __uint_as_float(v & 0xffff0000u);
                    float2 d2 = *(const float2*)&dpb[2 * q];
                    float2 g2 = *(const float2*)&gv[2 * q];
                    acc += g2.x * tanh_ap(lo + d2.x);
                    acc += g2.y * tanh_ap(hi + d2.y);
                }
#pragma unroll
                for (int o = 16; o; o >>= 1) acc += __shfl_xor_sync(~0u, acc, o);
                if (lane == 0) g_escore[r] = acc;
            }
        }
        gbar(++ep);

        // ===== P2: softmax + att_c + x0 build  |  cell1(l-1) =====
        if (bid < 128) {
            int b = bid >> 3, ec = bid & 7;
            int hlen = hlens[b];
            float* s_w  = xs;          // 800
            float* s_at = xs + 1024;   // 1024
            const float* e = &g_escore[b * 800];
            float mx = -1e30f;
            for (int t = tid; t < 800; t += NTH)
                if (t < hlen) mx = fmaxf(mx, e[t]);
#pragma unroll
            for (int o = 16; o; o >>= 1) mx = fmaxf(mx, __shfl_xor_sync(~0u, mx, o));
            if (lane == 0) s_red[wid] = mx;
            __syncthreads();
            if (tid == 0) { float m = s_red[0]; for (int i = 1; i < 16; i++) m = fmaxf(m, s_red[i]); s_bc[0] = m; }
            __syncthreads();
            mx = s_bc[0];
            float sum = 0.f;
            for (int t = tid; t < 800; t += NTH) {
                float w = (t < hlen) ? __expf(2.0f * (e[t] - mx)) : 0.f;
                s_w[t] = w;
                sum += w;
            }
#pragma unroll
            for (int o = 16; o; o >>= 1) sum += __shfl_xor_sync(~0u, sum, o);
            if (lane == 0) s_red[wid] = sum;
            __syncthreads();
            if (tid == 0) { float s = 0.f; for (int i = 0; i < 16; i++) s += s_red[i]; s_bc[1] = 1.0f / s; }
            __syncthreads();
            float inv = s_bc[1];
            for (int t = tid; t < 800; t += NTH) s_w[t] *= inv;
            __syncthreads();
            // att_c for 64-e slice: ee = lane (uint pair), tt = wid (t stride 16)
            {
                const unsigned* hp = (const unsigned*)g_hs_bf + (size_t)b * 800 * 256 + ec * 32 + lane;
                float a0 = 0.f, a1 = 0.f;
#pragma unroll 5
                for (int t = wid; t < 800; t += 16) {
                    unsigned v = hp[(size_t)t * 256];
                    float w = s_w[t];
                    a0 = fmaf(w, __uint_as_float(v << 16), a0);
                    a1 = fmaf(w, __uint_as_float(v & 0xffff0000u), a1);
                }
                *(float2*)&s_at[wid * 64 + lane * 2] = make_float2(a0, a1);
            }
            __syncthreads();
            if (tid < 64) {
                float s = 0.f;
#pragma unroll
                for (int y = 0; y < 16; y++) s += s_at[y * 64 + tid];
                g_x0[b * 2560 + 1024 + ec * 64 + tid] = s;
            }
            // x0 [ey | . | z0] slice: 256 of 32768
            if (tid < 256) {
                int idx = bid * 256 + tid;
                int b2 = idx >> 11, r2 = idx & 2047;
                if (r2 < 1024) g_x0[b2 * 2560 + r2] = g_eys[((size_t)b2 * LL + l) * 1024 + r2];
                else g_x0[b2 * 2560 + 1536 + (r2 - 1024)] = g_z0[b2 * 1024 + (r2 - 1024)];
            }
        } else if (l > 0) {
            // cell1(l-1): blocks 128..147, 1024 elems each (20*1024 >= 16384)
            int base = (bid - 128) * 1024;
            for (int i = tid; i < 1024; i += NTH) {
                int u = base + i;
                if (u < 16384) do_cell1(u, l - 1);
            }
        }
        gbar(++ep);

        // ===== P3: gates0 (128 vbs: jg4 x ks32, kchunk 80) =====
        if (bid < 128) skinny_ffma2<2>(g_x0, g_W0P, g_part0, 2560, 4096, KC0, bid & 3, bid >> 2, xs);
        gbar(++ep);

        // ===== P4: cell0 + x1 build (32 vbs) =====
        if (bid < 32) do_cell0(bid * NTH + tid);
        gbar(++ep);

        // ===== P5: gates1 (128 vbs) + dec_proj next step (8 vbs) =====
        if (bid < 128)      skinny_ffma2<2>(g_x1, g_W1P, g_part1, 2048, 4096, KC1, bid & 3, bid >> 2, xs);
        else if (bid < 136) skinny_ffma2<1>(g_z0, g_WdP, g_partd, 1024, 512, KCD, 0, bid - 128, xs);
        gbar(++ep);
    }

    // tail: cell1(LL-1)
    if (bid < 32) do_cell1(bid * NTH + tid, LL - 1);
}

// ---------------- epilogue ----------------
__global__ __launch_bounds__(256) void nll_kernel(const int* __restrict__ ys_pad) {
    __shared__ float red[256];
    int m = blockIdx.x, tid = threadIdx.x;
    int b = m / LL, l = m % LL;
    const float* row = &g_logits[(size_t)m * OO];
    float mx = -1e30f;
    for (int i = tid; i < OO; i += 256) mx = fmaxf(mx, row[i]);
    red[tid] = mx; __syncthreads();
    for (int s = 128; s; s >>= 1) { if (tid < s) red[tid] = fmaxf(red[tid], red[tid + s]); __syncthreads(); }
    mx = red[0]; __syncthreads();
    float sum = 0.f;
    for (int i = tid; i < OO; i += 256) sum += __expf(row[i] - mx);
    red[tid] = sum; __syncthreads();
    for (int s = 128; s; s >>= 1) { if (tid < s) red[tid] += red[tid + s]; __syncthreads(); }
    if (tid == 0) {
        int tgt = (l < 96) ? ys_pad[b * 96 + l] : SOSEOS;
        g_nll[m] = logf(red[0]) + mx - row[tgt];
    }
}
__global__ __launch_bounds__(256) void finalize(float* out) {
    __shared__ float red[256];
    int tid = threadIdx.x;
    float acc = 0.f;
    for (int i = tid; i < BB * LL; i += 256) acc += g_nll[i];
    red[tid] = acc; __syncthreads();
    for (int s = 128; s; s >>= 1) { if (tid < s) red[tid] += red[tid + s]; __syncthreads(); }
    if (tid == 0) out[0] = red[0] * (96.0f / (float)(BB * LL));
}

// ---------------- launch ----------------
extern "C" void kernel_launch(void* const* d_in, const int* in_sizes, int n_in,
                              void* d_out, int out_size) {
    const float* hs_pad = (const float*)d_in[0];
    const int*   hlens  = (const int*)d_in[1];
    const int*   ys_pad = (const int*)d_in[2];
    const float* embed  = (const float*)d_in[3];
    const float* W_ih0  = (const float*)d_in[4];
    const float* W_hh0  = (const float*)d_in[5];
    const float* b_ih0  = (const float*)d_in[6];
    const float* b_hh0  = (const float*)d_in[7];
    const float* W_ih1  = (const float*)d_in[8];
    const float* W_hh1  = (const float*)d_in[9];
    const float* b_ih1  = (const float*)d_in[10];
    const float* b_hh1  = (const float*)d_in[11];
    const float* W_enc  = (const float*)d_in[12];
    const float* b_enc  = (const float*)d_in[13];
    const float* W_dec  = (const float*)d_in[14];
    const float* gvec   = (const float*)d_in[15];
    const float* W_out  = (const float*)d_in[16];
    const float* b_out  = (const float*)d_in[17];
    float* out = (float*)d_out;

    pack_w0<<<(4096 * 2560 + 255) / 256, 256>>>(W_ih0, W_hh0);
    pack_w1<<<(4096 * 2048 + 255) / 256, 256>>>(W_ih1, W_hh1);
    pack_wd<<<(512 * 1024 + 255) / 256, 256>>>(W_dec);
    convert_hs<<<(BB * TT * EE + 255) / 256, 256>>>(hs_pad);
    prep_misc<<<(BB * LL * DD + 255) / 256, 256>>>(b_ih0, b_hh0, b_ih1, b_hh1, ys_pad, embed);

    // pre_enc = hs_pad @ W_enc^T + b_enc -> bf16
    gemm_nt<1><<<dim3(4, 100), 256>>>(hs_pad, W_enc, b_enc, nullptr, g_preenc_bf, BB * TT, AA, EE);

    // all 97 recurrent steps in one persistent kernel
    decoder_loop<<<NBLK, NTH>>>(hlens, gvec);

    // logits = z_all @ W_out^T + b_out
    gemm_nt<0><<<dim3(40, 13), 256>>>(g_zall, W_out, b_out, g_logits, nullptr, BB * LL, OO, DD);
    nll_kernel<<<BB * LL, 256>>>(ys_pad);
    finalize<<<1, 256>>>(out);
}

// round 6
// speedup vs baseline: 8.7645x; 1.2777x over previous
#include <cuda_runtime.h>
#include <cuda_bf16.h>
#include <math.h>
#include <stdint.h>

#define BB 16
#define TT 800
#define EE 512
#define DD 1024
#define AA 512
#define OO 5000
#define LL 97
#define SOSEOS 4999
#define NBLK 148
#define NTH 512

// x strides (bf16 elems, padded +8 for ldmatrix bank spread)
#define XS0 2568   // K0=2560
#define XS1 2056   // K1=2048
#define XSD 1032   // Kd=1024
#define RED_OFF 83968
#define SMEM_BYTES 92160

// ---------------- scratch ----------------
__device__ __align__(16) unsigned short g_preenc_bf[BB * TT * AA];
__device__ __align__(16) unsigned short g_hs_bf[BB * TT * EE];
__device__ __align__(16) unsigned short g_W0F[4096 * 2560];   // mma B-fragment layout
__device__ __align__(16) unsigned short g_W1F[4096 * 2048];
__device__ __align__(16) unsigned short g_WdF[512 * 1024];
__device__ __align__(16) unsigned short g_eys_bf[BB * LL * DD];
__device__ __align__(16) unsigned short g_z0bf[BB * DD], g_z1bf[BB * DD];
__device__ __align__(16) unsigned short g_attc_bf[BB * AA];
__device__ __align__(16) unsigned short g_x1bf[BB * 2048];
__device__ float g_b0[4096], g_b1[4096];
__device__ float g_c0[BB * DD], g_c1[BB * DD];
__device__ float g_dp[BB * AA];
__device__ float g_escore[BB * TT];
__device__ float g_zall[BB * LL * DD];
__device__ float g_logits[(size_t)BB * LL * OO];
__device__ float g_nll[BB * LL];
__device__ volatile unsigned g_arr[NBLK];
__device__ volatile unsigned g_rel;

// ---------------- helpers ----------------
__device__ __forceinline__ float tanh_ap(float x) {
    float y; asm("tanh.approx.f32 %0, %1;" : "=f"(y) : "f"(x)); return y;
}
__device__ __forceinline__ float sigm(float x) { return 1.0f / (1.0f + __expf(-x)); }
__device__ __forceinline__ unsigned short f2bf(float v) {
    return __bfloat16_as_ushort(__float2bfloat16_rn(v));
}

// device-wide barrier (148 co-resident blocks)
__device__ __forceinline__ void gbar(unsigned ep) {
    __syncthreads();
    if (threadIdx.x == 0) {
        __threadfence();
        g_arr[blockIdx.x] = ep;
    }
    if (blockIdx.x == 0) {
        if (threadIdx.x < NBLK) {
            while (g_arr[threadIdx.x] < ep) { }
        }
        __syncthreads();
        if (threadIdx.x == 0) { __threadfence(); g_rel = ep; }
    }
    if (threadIdx.x == 0) {
        while (g_rel < ep) { }
        __threadfence();
    }
    __syncthreads();
}

// ---------------- prolog: pack weights into mma B-fragment layout ----------------
// frag buffer = uint4[(jt*(K/32) + ktp)*32 + lane]; per (j,k):
//   jt=j/8, n=j%8, kt=k/16, kk=k%16, lane=n*4+((kk&7)>>1),
//   comp=((kt&1)<<1)+(kk>>3), half=kk&1  -> ushort idx = base*8 + comp*2 + half
__global__ void pack_frag(const float* __restrict__ Wa, const float* __restrict__ Wb,
                          int Ka, int K, int N, unsigned short* __restrict__ dst) {
    int idx = blockIdx.x * 256 + threadIdx.x;
    if (idx >= N * K) return;
    int j = idx / K, k = idx - j * K;
    float v = (k < Ka) ? Wa[(size_t)j * Ka + k] : Wb[(size_t)j * (K - Ka) + (k - Ka)];
    int jt = j >> 3, n = j & 7, kt = k >> 4, kk = k & 15;
    int lane = n * 4 + ((kk & 7) >> 1);
    int comp = ((kt & 1) << 1) + (kk >> 3);
    size_t base = ((size_t)jt * (K >> 5) + (kt >> 1)) * 32 + lane;
    dst[base * 8 + comp * 2 + (kk & 1)] = f2bf(v);
}
__global__ void convert_hs(const float* __restrict__ hs) {
    int idx = blockIdx.x * 256 + threadIdx.x;
    if (idx < BB * TT * EE) g_hs_bf[idx] = f2bf(hs[idx]);
}
__global__ void prep_misc(const float* __restrict__ bih0, const float* __restrict__ bhh0,
                          const float* __restrict__ bih1, const float* __restrict__ bhh1,
                          const int* __restrict__ ys_pad, const float* __restrict__ embed) {
    int idx = blockIdx.x * 256 + threadIdx.x;
    if (idx < 4096) {
        g_b0[idx] = bih0[idx] + bhh0[idx];
        g_b1[idx] = bih1[idx] + bhh1[idx];
    }
    if (idx < BB * DD) {
        g_c0[idx] = 0.f; g_c1[idx] = 0.f;
        g_z0bf[idx] = 0; g_z1bf[idx] = 0;
    }
    if (idx < BB * AA) g_dp[idx] = 0.f;
    if (idx < NBLK) g_arr[idx] = 0u;
    if (idx == 0) g_rel = 0u;
    if (idx < BB * LL * DD) {
        int m = idx >> 10, d = idx & 1023;
        int b = m / LL, l = m % LL;
        int tok = (l == 0) ? SOSEOS : ys_pad[b * 96 + l - 1];
        g_eys_bf[idx] = f2bf(embed[(size_t)tok * DD + d]);
    }
}

// ---------------- generic NT GEMM (pre_enc + logits) ----------------
template <int STORE_BF>
__global__ __launch_bounds__(256) void gemm_nt(const float* __restrict__ A,
                                               const float* __restrict__ Bm,
                                               const float* __restrict__ bias,
                                               float* __restrict__ C,
                                               unsigned short* __restrict__ Cbf,
                                               int M, int N, int K) {
    __shared__ float As[8][128];
    __shared__ float Bs[8][128];
    int tid = threadIdx.x;
    int m0 = blockIdx.y * 128, n0 = blockIdx.x * 128;
    int lr = tid >> 1, lk = (tid & 1) * 4;
    int tx = tid & 15, ty = tid >> 4;
    float acc[8][8];
#pragma unroll
    for (int i = 0; i < 8; i++)
#pragma unroll
        for (int j = 0; j < 8; j++) acc[i][j] = 0.f;
    for (int k0 = 0; k0 < K; k0 += 8) {
        float4 av = make_float4(0.f,0.f,0.f,0.f), bv = make_float4(0.f,0.f,0.f,0.f);
        if (m0 + lr < M) av = *(const float4*)&A[(size_t)(m0 + lr) * K + k0 + lk];
        if (n0 + lr < N) bv = *(const float4*)&Bm[(size_t)(n0 + lr) * K + k0 + lk];
        __syncthreads();
        As[lk+0][lr]=av.x; As[lk+1][lr]=av.y; As[lk+2][lr]=av.z; As[lk+3][lr]=av.w;
        Bs[lk+0][lr]=bv.x; Bs[lk+1][lr]=bv.y; Bs[lk+2][lr]=bv.z; Bs[lk+3][lr]=bv.w;
        __syncthreads();
#pragma unroll
        for (int kk = 0; kk < 8; kk++) {
            float a[8], b[8];
            *(float4*)(a)   = *(const float4*)&As[kk][ty*8];
            *(float4*)(a+4) = *(const float4*)&As[kk][ty*8+4];
            *(float4*)(b)   = *(const float4*)&Bs[kk][tx*8];
            *(float4*)(b+4) = *(const float4*)&Bs[kk][tx*8+4];
#pragma unroll
            for (int i = 0; i < 8; i++)
#pragma unroll
                for (int j = 0; j < 8; j++) acc[i][j] += a[i] * b[j];
        }
    }
#pragma unroll
    for (int i = 0; i < 8; i++) {
        int m = m0 + ty*8 + i;
        if (m >= M) continue;
#pragma unroll
        for (int j = 0; j < 8; j++) {
            int n = n0 + tx*8 + j;
            if (n < N) {
                float v = acc[i][j] + bias[n];
                if (STORE_BF) Cbf[(size_t)m * N + n] = f2bf(v);
                else          C[(size_t)m * N + n] = v;
            }
        }
    }
}

// ---------------- warp-level mma over one n8 tile, k-slice ----------------
__device__ __forceinline__ void warp_mma(const uint4* __restrict__ wf, int KT32, int jt,
                                         int ktp0, int nktp, const unsigned short* xs,
                                         int XSTR, int lane, float* c) {
    int m = lane >> 3, r = lane & 7;
    int row = r + ((m & 1) << 3);
    int colh = m >> 1;
    unsigned sbase = (unsigned)__cvta_generic_to_shared(xs) + (unsigned)((row * XSTR + colh * 8) * 2);
    const uint4* wp = wf + (size_t)jt * KT32 * 32 + lane;
#pragma unroll 4
    for (int t = 0; t < nktp; t++) {
        int ktp = ktp0 + t;
        unsigned a0,a1,a2,a3, e0,e1,e2,e3;
        unsigned addr0 = sbase + (unsigned)(ktp * 64);
        asm volatile("ldmatrix.sync.aligned.m8n8.x4.shared.b16 {%0,%1,%2,%3}, [%4];"
            : "=r"(a0),"=r"(a1),"=r"(a2),"=r"(a3) : "r"(addr0));
        asm volatile("ldmatrix.sync.aligned.m8n8.x4.shared.b16 {%0,%1,%2,%3}, [%4];"
            : "=r"(e0),"=r"(e1),"=r"(e2),"=r"(e3) : "r"(addr0 + 32u));
        uint4 wv = wp[(size_t)ktp * 32];
        asm volatile("mma.sync.aligned.m16n8k16.row.col.f32.bf16.bf16.f32 "
            "{%0,%1,%2,%3}, {%4,%5,%6,%7}, {%8,%9}, {%0,%1,%2,%3};"
            : "+f"(c[0]),"+f"(c[1]),"+f"(c[2]),"+f"(c[3])
            : "r"(a0),"r"(a1),"r"(a2),"r"(a3), "r"(wv.x),"r"(wv.y));
        asm volatile("mma.sync.aligned.m16n8k16.row.col.f32.bf16.bf16.f32 "
            "{%0,%1,%2,%3}, {%4,%5,%6,%7}, {%8,%9}, {%0,%1,%2,%3};"
            : "+f"(c[0]),"+f"(c[1]),"+f"(c[2]),"+f"(c[3])
            : "r"(e0),"r"(e1),"r"(e2),"r"(e3), "r"(wv.z),"r"(wv.w));
    }
}

// ---------------- persistent decoder loop ----------------
extern "C" __global__ void __launch_bounds__(NTH, 1)
decoder_loop(const int* __restrict__ hlens, const float* __restrict__ gvec) {
    extern __shared__ __align__(16) char smem[];
    __shared__ float s_red[16];
    __shared__ float s_bc[2];
    const int bid = blockIdx.x, tid = threadIdx.x;
    const int lane = tid & 31, wid = tid >> 5;
    unsigned ep = 0;

    for (int l = 0; l < LL; l++) {
        // ===== P1: e[b,t] = sum_a gvec[a]*tanh(pre_enc + dp) =====
        {
            int r0 = bid * 86 + min(bid, 72);
            int nr = 86 + (bid < 72 ? 1 : 0);
            int b0 = r0 / 800;
            float* dp = (float*)smem;            // 1024
            float* gv = (float*)(smem + 4096);   // 512
            for (int a = tid; a < 512; a += NTH) {
                dp[a] = g_dp[b0 * 512 + a];
                dp[512 + a] = (b0 + 1 < 16) ? g_dp[(b0 + 1) * 512 + a] : 0.f;
                gv[a] = gvec[a];
            }
            __syncthreads();
            for (int r = r0 + wid; r < r0 + nr; r += 16) {
                int b = r / 800;
                const unsigned* pe = (const unsigned*)g_preenc_bf + (size_t)r * 256;
                const float* dpb = dp + (b - b0) * 512;
                float acc = 0.f;
#pragma unroll
                for (int p = 0; p < 8; p++) {
                    int q = lane + 32 * p;
                    unsigned v = pe[q];
                    float lo = __uint_as_float(v << 16);
                    float hi = __uint_as_float(v & 0xffff0000u);
                    float2 d2 = *(const float2*)&dpb[2 * q];
                    float2 g2 = *(const float2*)&gv[2 * q];
                    acc += g2.x * tanh_ap(lo + d2.x);
                    acc += g2.y * tanh_ap(hi + d2.y);
                }
#pragma unroll
                for (int o = 16; o; o >>= 1) acc += __shfl_xor_sync(~0u, acc, o);
                if (lane == 0) g_escore[r] = acc;
            }
        }
        gbar(++ep);

        // ===== P2: softmax + att_c (bf16) =====
        if (bid < 128) {
            int b = bid >> 3, ec = bid & 7;
            int hlen = hlens[b];
            float* s_w  = (float*)smem;            // 800
            float* s_at = (float*)(smem + 4096);   // 1024
            const float* e = &g_escore[b * 800];
            float mx = -1e30f;
            for (int t = tid; t < 800; t += NTH)
                if (t < hlen) mx = fmaxf(mx, e[t]);
#pragma unroll
            for (int o = 16; o; o >>= 1) mx = fmaxf(mx, __shfl_xor_sync(~0u, mx, o));
            if (lane == 0) s_red[wid] = mx;
            __syncthreads();
            if (tid == 0) { float m = s_red[0]; for (int i = 1; i < 16; i++) m = fmaxf(m, s_red[i]); s_bc[0] = m; }
            __syncthreads();
            mx = s_bc[0];
            float sum = 0.f;
            for (int t = tid; t < 800; t += NTH) {
                float w = (t < hlen) ? __expf(2.0f * (e[t] - mx)) : 0.f;
                s_w[t] = w;
                sum += w;
            }
#pragma unroll
            for (int o = 16; o; o >>= 1) sum += __shfl_xor_sync(~0u, sum, o);
            if (lane == 0) s_red[wid] = sum;
            __syncthreads();
            if (tid == 0) { float s = 0.f; for (int i = 0; i < 16; i++) s += s_red[i]; s_bc[1] = 1.0f / s; }
            __syncthreads();
            float inv = s_bc[1];
            for (int t = tid; t < 800; t += NTH) s_w[t] *= inv;
            __syncthreads();
            {
                const unsigned* hp = (const unsigned*)g_hs_bf + (size_t)b * 800 * 256 + ec * 32 + lane;
                float a0 = 0.f, a1 = 0.f;
#pragma unroll 5
                for (int t = wid; t < 800; t += 16) {
                    unsigned v = hp[(size_t)t * 256];
                    float w = s_w[t];
                    a0 = fmaf(w, __uint_as_float(v << 16), a0);
                    a1 = fmaf(w, __uint_as_float(v & 0xffff0000u), a1);
                }
                *(float2*)&s_at[wid * 64 + lane * 2] = make_float2(a0, a1);
            }
            __syncthreads();
            if (tid < 64) {
                float s = 0.f;
#pragma unroll
                for (int y = 0; y < 16; y++) s += s_at[y * 64 + tid];
                g_attc_bf[b * 512 + ec * 64 + tid] = f2bf(s);
            }
        }
        gbar(++ep);

        // ===== P3: gates0 + cell0 (128 blocks x 8 d, full K=2560) =====
        if (bid < 128) {
            unsigned short* xs = (unsigned short*)smem;
            float* red = (float*)(smem + RED_OFF);
            uint4* xd = (uint4*)xs;
            for (int i = tid; i < 5120; i += NTH) {
                int b = i / 320, q = i - b * 320;
                uint4 v;
                if (q < 128)      v = ((const uint4*)g_eys_bf)[(size_t)(b * LL + l) * 128 + q];
                else if (q < 192) v = ((const uint4*)g_attc_bf)[b * 64 + (q - 128)];
                else              v = ((const uint4*)g_z0bf)[b * 128 + (q - 192)];
                xd[b * 321 + q] = v;
            }
            __syncthreads();
            int g = wid & 3, ks = wid >> 2;
            float c[4] = {0.f, 0.f, 0.f, 0.f};
            warp_mma((const uint4*)g_W0F, 80, g * 128 + bid, ks * 20, 20, xs, XS0, lane, c);
            float* rw = &red[(wid * 32 + lane) * 4];
            rw[0] = c[0]; rw[1] = c[1]; rw[2] = c[2]; rw[3] = c[3];
            __syncthreads();
            if (tid < 128) {
                int b = tid >> 3, dl = tid & 7, d = bid * 8 + dl;
                int lr = (b & 7) * 4 + (dl >> 1);
                int rg = ((b >> 3) << 1) + (dl & 1);
                float gv4[4];
#pragma unroll
                for (int gg = 0; gg < 4; gg++) {
                    float s = 0.f;
#pragma unroll
                    for (int k2 = 0; k2 < 4; k2++) s += red[((k2 * 4 + gg) * 32 + lr) * 4 + rg];
                    gv4[gg] = s;
                }
                float gi = gv4[0] + g_b0[d], gf = gv4[1] + g_b0[1024 + d];
                float gg = gv4[2] + g_b0[2048 + d], go = gv4[3] + g_b0[3072 + d];
                int u = b * 1024 + d;
                float cc = sigm(gf) * g_c0[u] + sigm(gi) * tanh_ap(gg);
                float h = sigm(go) * tanh_ap(cc);
                g_c0[u] = cc;
                unsigned short hb = f2bf(h);
                g_z0bf[u] = hb;
                g_x1bf[b * 2048 + d] = hb;
                g_x1bf[b * 2048 + 1024 + d] = g_z1bf[u];
            }
        }
        gbar(++ep);

        // ===== P4: gates1+cell1 (128 blocks) | dec_proj (16 blocks) =====
        if (bid < 128) {
            unsigned short* xs = (unsigned short*)smem;
            float* red = (float*)(smem + RED_OFF);
            uint4* xd = (uint4*)xs;
            for (int i = tid; i < 4096; i += NTH) {
                int b = i >> 8, q = i & 255;
                xd[b * 257 + q] = ((const uint4*)g_x1bf)[b * 256 + q];
            }
            __syncthreads();
            int g = wid & 3, ks = wid >> 2;
            float c[4] = {0.f, 0.f, 0.f, 0.f};
            warp_mma((const uint4*)g_W1F, 64, g * 128 + bid, ks * 16, 16, xs, XS1, lane, c);
            float* rw = &red[(wid * 32 + lane) * 4];
            rw[0] = c[0]; rw[1] = c[1]; rw[2] = c[2]; rw[3] = c[3];
            __syncthreads();
            if (tid < 128) {
                int b = tid >> 3, dl = tid & 7, d = bid * 8 + dl;
                int lr = (b & 7) * 4 + (dl >> 1);
                int rg = ((b >> 3) << 1) + (dl & 1);
                float gv4[4];
#pragma unroll
                for (int gg = 0; gg < 4; gg++) {
                    float s = 0.f;
#pragma unroll
                    for (int k2 = 0; k2 < 4; k2++) s += red[((k2 * 4 + gg) * 32 + lr) * 4 + rg];
                    gv4[gg] = s;
                }
                float gi = gv4[0] + g_b1[d], gf = gv4[1] + g_b1[1024 + d];
                float gg = gv4[2] + g_b1[2048 + d], go = gv4[3] + g_b1[3072 + d];
                int u = b * 1024 + d;
                float cc = sigm(gf) * g_c1[u] + sigm(gi) * tanh_ap(gg);
                float h = sigm(go) * tanh_ap(cc);
                g_c1[u] = cc;
                g_z1bf[u] = f2bf(h);
                g_zall[((size_t)b * LL + l) * 1024 + d] = h;
            }
        } else if (bid < 144) {
            unsigned short* xs = (unsigned short*)smem;
            float* red = (float*)(smem + RED_OFF);
            uint4* xd = (uint4*)xs;
            for (int i = tid; i < 2048; i += NTH) {
                int b = i >> 7, q = i & 127;
                xd[b * 129 + q] = ((const uint4*)g_z0bf)[b * 128 + q];
            }
            __syncthreads();
            int ti = wid & 3, ks = wid >> 2;
            float c[4] = {0.f, 0.f, 0.f, 0.f};
            warp_mma((const uint4*)g_WdF, 32, (bid - 128) * 4 + ti, ks * 8, 8, xs, XSD, lane, c);
            float* rw = &red[(wid * 32 + lane) * 4];
            rw[0] = c[0]; rw[1] = c[1]; rw[2] = c[2]; rw[3] = c[3];
            __syncthreads();
            {
                int ti2 = tid >> 7, rem = tid & 127;
                int b = rem >> 3, al = rem & 7;
                int lr = (b & 7) * 4 + (al >> 1);
                int rg = ((b >> 3) << 1) + (al & 1);
                float s = 0.f;
#pragma unroll
                for (int k2 = 0; k2 < 4; k2++) s += red[((k2 * 4 + ti2) * 32 + lr) * 4 + rg];
                g_dp[b * 512 + (bid - 128) * 32 + ti2 * 8 + al] = s;
            }
        }
        gbar(++ep);
    }
}

// ---------------- epilogue ----------------
__global__ __launch_bounds__(256) void nll_kernel(const int* __restrict__ ys_pad) {
    __shared__ float red[256];
    int m = blockIdx.x, tid = threadIdx.x;
    int b = m / LL, l = m % LL;
    const float* row = &g_logits[(size_t)m * OO];
    float mx = -1e30f;
    for (int i = tid; i < OO; i += 256) mx = fmaxf(mx, row[i]);
    red[tid] = mx; __syncthreads();
    for (int s = 128; s; s >>= 1) { if (tid < s) red[tid] = fmaxf(red[tid], red[tid + s]); __syncthreads(); }
    mx = red[0]; __syncthreads();
    float sum = 0.f;
    for (int i = tid; i < OO; i += 256) sum += __expf(row[i] - mx);
    red[tid] = sum; __syncthreads();
    for (int s = 128; s; s >>= 1) { if (tid < s) red[tid] += red[tid + s]; __syncthreads(); }
    if (tid == 0) {
        int tgt = (l < 96) ? ys_pad[b * 96 + l] : SOSEOS;
        g_nll[m] = logf(red[0]) + mx - row[tgt];
    }
}
__global__ __launch_bounds__(256) void finalize(float* out) {
    __shared__ float red[256];
    int tid = threadIdx.x;
    float acc = 0.f;
    for (int i = tid; i < BB * LL; i += 256) acc += g_nll[i];
    red[tid] = acc; __syncthreads();
    for (int s = 128; s; s >>= 1) { if (tid < s) red[tid] += red[tid + s]; __syncthreads(); }
    if (tid == 0) out[0] = red[0] * (96.0f / (float)(BB * LL));
}

// ---------------- launch ----------------
extern "C" void kernel_launch(void* const* d_in, const int* in_sizes, int n_in,
                              void* d_out, int out_size) {
    const float* hs_pad = (const float*)d_in[0];
    const int*   hlens  = (const int*)d_in[1];
    const int*   ys_pad = (const int*)d_in[2];
    const float* embed  = (const float*)d_in[3];
    const float* W_ih0  = (const float*)d_in[4];
    const float* W_hh0  = (const float*)d_in[5];
    const float* b_ih0  = (const float*)d_in[6];
    const float* b_hh0  = (const float*)d_in[7];
    const float* W_ih1  = (const float*)d_in[8];
    const float* W_hh1  = (const float*)d_in[9];
    const float* b_ih1  = (const float*)d_in[10];
    const float* b_hh1  = (const float*)d_in[11];
    const float* W_enc  = (const float*)d_in[12];
    const float* b_enc  = (const float*)d_in[13];
    const float* W_dec  = (const float*)d_in[14];
    const float* gvec   = (const float*)d_in[15];
    const float* W_out  = (const float*)d_in[16];
    const float* b_out  = (const float*)d_in[17];
    float* out = (float*)d_out;

    static unsigned short* w0f = nullptr;
    if (!w0f) {
        cudaGetSymbolAddress((void**)&w0f, g_W0F);  // just to force symbol use; ignore
    }

    unsigned short *d_w0f, *d_w1f, *d_wdf;
    cudaGetSymbolAddress((void**)&d_w0f, g_W0F);
    cudaGetSymbolAddress((void**)&d_w1f, g_W1F);
    cudaGetSymbolAddress((void**)&d_wdf, g_WdF);

    pack_frag<<<(4096 * 2560 + 255) / 256, 256>>>(W_ih0, W_hh0, 1536, 2560, 4096, d_w0f);
    pack_frag<<<(4096 * 2048 + 255) / 256, 256>>>(W_ih1, W_hh1, 1024, 2048, 4096, d_w1f);
    pack_frag<<<(512 * 1024 + 255) / 256, 256>>>(W_dec, W_dec, 1024, 1024, 512, d_wdf);
    convert_hs<<<(BB * TT * EE + 255) / 256, 256>>>(hs_pad);
    prep_misc<<<(BB * LL * DD + 255) / 256, 256>>>(b_ih0, b_hh0, b_ih1, b_hh1, ys_pad, embed);

    // pre_enc = hs_pad @ W_enc^T + b_enc -> bf16
    gemm_nt<1><<<dim3(4, 100), 256>>>(hs_pad, W_enc, b_enc, nullptr, g_preenc_bf, BB * TT, AA, EE);

    // all 97 recurrent steps in one persistent kernel
    cudaFuncSetAttribute(decoder_loop, cudaFuncAttributeMaxDynamicSharedMemorySize, SMEM_BYTES);
    decoder_loop<<<NBLK, NTH, SMEM_BYTES>>>(hlens, gvec);

    // logits = z_all @ W_out^T + b_out
    gemm_nt<0><<<dim3(40, 13), 256>>>(g_zall, W_out, b_out, g_logits, nullptr, BB * LL, OO, DD);
    nll_kernel<<<BB * LL, 256>>>(ys_pad);
    finalize<<<1, 256>>>(out);
}